// round 12
// baseline (speedup 1.0000x reference)
#include <cuda_runtime.h>
#include <math.h>

#define BB 32
#define TT 512
#define TT1 513
#define SD 256
#define HD 512
#define BT (BB*TT)
#define MS (BT*SD)
#define MT (BT*TT)
#define NB 32

__device__ __align__(128) float g_st[MS], g_se[MS], g_tp[MS], g_tc[MS], g_gg[MS];
__device__ __align__(128) float g_A[MT], g_L[MT], g_Li[MT], g_cat[MT], g_cat2[MT];
__device__ __align__(128) float g_P[2*BB*TT*NB];
__device__ __align__(128) float g_cs[BT], g_ar[BT], g_dg[BT];
__device__ __align__(128) int   g_piv[BT];
__device__ __align__(128) int   g_srcrow[2*BT];

// ---------------- elementwise ----------------
__global__ void split_k(const float* __restrict__ x) {
  int idx = blockIdx.x*blockDim.x + threadIdx.x;
  int c = idx & 511; int bt = idx >> 9;
  const float* xp = x + (size_t)bt*HD;
  if (c < SD) g_se[(size_t)bt*SD + c] = xp[c + ((c >= 128) ? 128 : 0)];
  else { int cc = c - SD; g_st[(size_t)bt*SD + cc] = xp[cc + 128 + ((cc >= 128) ? 128 : 0)]; }
}

__global__ void root_k(const float* __restrict__ wr, const int* __restrict__ seq) {
  int g = blockIdx.x*blockDim.x + threadIdx.x;
  int w = g >> 5, lane = g & 31;
  if (w >= BT) return;
  const float* s = g_st + (size_t)w*SD;
  float acc = 0.f;
  for (int c = lane; c < SD; c += 32) acc += s[c]*wr[c];
  for (int o = 16; o > 0; o >>= 1) acc += __shfl_down_sync(0xffffffffu, acc, o);
  if (lane == 0) {
    int b = w >> 9, t = w & 511;
    g_ar[w] = (t < seq[b]) ? expf(acc) : 0.0f;
  }
}

__global__ void zcs_k() {
  g_cs[blockIdx.x*1024 + threadIdx.x] = 0.0f;
}

__global__ void colsum_k() {
  int b = blockIdx.y, j = threadIdx.x;
  int i0 = blockIdx.x*64;
  const float* a = g_A + (size_t)b*TT*TT;
  float s = 0.f;
  #pragma unroll 8
  for (int i = i0; i < i0+64; ++i) s += a[(size_t)i*TT + j];
  atomicAdd(&g_cs[b*TT + j], s);
}

__global__ void buildL_k(const int* __restrict__ seq) {
  int idx = blockIdx.x*blockDim.x + threadIdx.x;
  int j = idx & 511, i = (idx >> 9) & 511, b = idx >> 18;
  float v;
  if (i == 0) v = g_ar[b*TT + j];
  else {
    v = -g_A[idx];
    if (i == j) v += g_cs[b*TT + j] + ((j >= seq[b]) ? 1.0f : 0.0f);
  }
  g_L[idx] = v;
}

// ---------------- blocked Gauss-Jordan inverse (NB=32, partial pivoting) ----------------
// panel_k: factor 512x32 block cols of srcM in smem, record sigma_r, write panel to pOut.
__global__ __launch_bounds__(1024) void panel_k(const float* __restrict__ srcM, int k0,
                                                float* __restrict__ pOutM,
                                                int* __restrict__ smapOutG) {
  extern __shared__ float panel[];  // 512 x 33
  __shared__ float colM[TT];
  __shared__ int rowmap[TT];
  __shared__ float redv[32]; __shared__ int redi[32];
  __shared__ int sIr;
  int b = blockIdx.x, tid = threadIdx.x;
  const float* src = srcM + (size_t)b*TT*TT;
  float* pOut = pOutM + (size_t)b*TT*NB;
  for (int idx = tid; idx < TT*NB; idx += 1024) {
    int i = idx >> 5, c = idx & 31;
    panel[i*33+c] = src[(size_t)i*TT + k0 + c];
  }
  if (tid < TT) rowmap[tid] = tid;
  __syncthreads();
  for (int kk = 0; kk < NB; ++kk) {
    int k = k0 + kk;
    float v = -1.0f; int ix = tid;
    if (tid < TT && tid >= k) v = fabsf(panel[tid*33+kk]);
    for (int o = 16; o > 0; o >>= 1) {
      float v2 = __shfl_down_sync(0xffffffffu, v, o);
      int   i2 = __shfl_down_sync(0xffffffffu, ix, o);
      if (v2 > v) { v = v2; ix = i2; }
    }
    if ((tid & 31) == 0) { redv[tid>>5] = v; redi[tid>>5] = ix; }
    __syncthreads();
    if (tid < 32) {
      float bv = redv[tid]; int bi = redi[tid];
      for (int o = 16; o > 0; o >>= 1) {
        float v2 = __shfl_down_sync(0xffffffffu, bv, o);
        int   i2 = __shfl_down_sync(0xffffffffu, bi, o);
        if (v2 > bv) { bv = v2; bi = i2; }
      }
      if (tid == 0) { sIr = bi; g_piv[b*TT+k] = bi; }
    }
    __syncthreads();
    int ir = sIr;
    if (tid < NB) {
      if (ir != k) {
        float t = panel[k*33+tid]; panel[k*33+tid] = panel[ir*33+tid]; panel[ir*33+tid] = t;
      }
      if (tid == 0 && ir != k) { int t = rowmap[k]; rowmap[k] = rowmap[ir]; rowmap[ir] = t; }
    }
    __syncthreads();
    if (tid < NB) {
      float pv  = panel[k*33+kk];
      float val = panel[k*33+tid];
      __syncwarp();
      float pinv = 1.0f / pv;
      if (tid == kk) val = 1.0f;
      panel[k*33+tid] = val * pinv;
    } else if (tid >= 64 && tid < 64+TT) {
      colM[tid-64] = panel[(tid-64)*33+kk];
    }
    __syncthreads();
    {
      int c = tid & 31;
      float rk = panel[k*33+c];
      for (int idx = tid; idx < TT*NB; idx += 1024) {
        int i = idx >> 5;
        if (i == k) continue;
        float m = colM[i];
        float cur = (c == kk) ? 0.0f : panel[i*33+c];
        panel[i*33+c] = cur - m*rk;
      }
    }
    __syncthreads();
  }
  if (tid < TT) smapOutG[b*TT + tid] = rowmap[tid];
  for (int idx = tid; idx < TT*NB; idx += 1024) {
    int i = idx >> 5, c = idx & 31;
    pOut[i*32+c] = panel[i*33+c];
  }
}

// update_k: DST[i][j] = [i not in blk]*SRC[sigma(i)][j] + P[i][:].R[:][j]
// jbaseP < 0 : rest mode (jbase = blockIdx.x*128). Cols blk(k0) copied from P; cols blk(k0skip) skipped.
// jbaseP >= 0: cols-only mode (32-wide slice at jbaseP).
__global__ __launch_bounds__(1024) void update_k(const float* __restrict__ srcM,
                                                 float* __restrict__ dstM,
                                                 const float* __restrict__ pM,
                                                 const int* __restrict__ smapG,
                                                 int k0, int k0skip, int jbaseP) {
  extern __shared__ float sm[];
  float* Ps = sm;           // 512 x 33
  float* Rs = sm + TT*33;   // 32 x 132
  __shared__ int smap[TT];
  int b = blockIdx.y, tid = threadIdx.x;
  int jbase = (jbaseP < 0) ? blockIdx.x*128 : jbaseP;
  int jw    = (jbaseP < 0) ? 128 : 32;
  const float* src = srcM + (size_t)b*TT*TT;
  float* dst = dstM + (size_t)b*TT*TT;
  const float* Pg = pM + (size_t)b*TT*NB;
  if (tid < TT) smap[tid] = smapG[b*TT + tid];
  __syncthreads();
  for (int idx = tid; idx < TT*NB; idx += 1024) {
    int i = idx >> 5, c = idx & 31;
    Ps[i*33+c] = Pg[i*32+c];
  }
  if (jw == 128) {
    for (int idx = tid; idx < NB*128; idx += 1024) {
      int k = idx >> 7, c = idx & 127;
      Rs[k*132+c] = src[(size_t)smap[k0+k]*TT + jbase + c];
    }
  } else {
    if (tid < NB*32) {
      int k = tid >> 5, c = tid & 31;
      Rs[k*132+c] = src[(size_t)smap[k0+k]*TT + jbase + c];
    }
  }
  __syncthreads();
  int tx = tid & 31, ty = tid >> 5;
  if (tx*4 >= jw) return;
  int j = jbase + tx*4;
  if (jbaseP < 0 && j >= k0 && j < k0 + NB) {
    // copy factored panel into DST block cols
    int pc = j - k0;
    for (int r = 0; r < 4; ++r) {
      int i0 = r*128 + ty*4;
#pragma unroll
      for (int q = 0; q < 4; ++q) {
        int i = i0 + q;
        *(float4*)(dst + (size_t)i*TT + j) = *(const float4*)(Pg + (size_t)i*32 + pc);
      }
    }
    return;
  }
  if (k0skip >= 0 && j >= k0skip && j < k0skip + NB) return;
  for (int r = 0; r < 4; ++r) {
    int i0 = r*128 + ty*4;
    float acc[4][4] = {};
#pragma unroll 8
    for (int k = 0; k < NB; ++k) {
      float4 rv = *(const float4*)(Rs + k*132 + tx*4);
      float p0 = Ps[(i0+0)*33+k], p1 = Ps[(i0+1)*33+k];
      float p2 = Ps[(i0+2)*33+k], p3 = Ps[(i0+3)*33+k];
      acc[0][0]+=p0*rv.x; acc[0][1]+=p0*rv.y; acc[0][2]+=p0*rv.z; acc[0][3]+=p0*rv.w;
      acc[1][0]+=p1*rv.x; acc[1][1]+=p1*rv.y; acc[1][2]+=p1*rv.z; acc[1][3]+=p1*rv.w;
      acc[2][0]+=p2*rv.x; acc[2][1]+=p2*rv.y; acc[2][2]+=p2*rv.z; acc[2][3]+=p2*rv.w;
      acc[3][0]+=p3*rv.x; acc[3][1]+=p3*rv.y; acc[3][2]+=p3*rv.z; acc[3][3]+=p3*rv.w;
    }
#pragma unroll
    for (int q = 0; q < 4; ++q) {
      int i = i0 + q;
      float4 res;
      if (i >= k0 && i < k0 + NB) res = make_float4(0.f,0.f,0.f,0.f);
      else res = *(const float4*)(src + (size_t)smap[i]*TT + j);
      res.x += acc[q][0]; res.y += acc[q][1]; res.z += acc[q][2]; res.w += acc[q][3];
      *(float4*)(dst + (size_t)i*TT + j) = res;
    }
  }
}

__global__ __launch_bounds__(1024) void gather_k() {
  __shared__ int arr[TT];
  int b = blockIdx.y, tid = threadIdx.x;
  if (tid == 0) {
    for (int j = 0; j < TT; ++j) arr[j] = j;
    for (int l = TT-1; l >= 0; --l) {
      int p = g_piv[b*TT + l];
      if (p != l) { int t = arr[l]; arr[l] = arr[p]; arr[p] = t; }
    }
  }
  __syncthreads();
  const float* a = g_L + (size_t)b*TT*TT;
  float* o = g_Li + (size_t)b*TT*TT;
  int base = blockIdx.x * 128 * TT;
  for (int idx = tid; idx < 128*TT; idx += 1024) {
    int i = idx >> 9, j = idx & 511;
    o[base + idx] = a[(size_t)(blockIdx.x*128 + i)*TT + arr[j]];
  }
}

__global__ void diag_k(float* __restrict__ out2) {
  int b = blockIdx.x, j = threadIdx.x;
  const float* L = g_Li + (size_t)b*TT*TT;
  g_dg[b*TT + j] = L[(size_t)j*TT + j];
  out2[(size_t)b*TT1*TT + j] = g_ar[b*TT + j] * L[(size_t)j*TT];
}

__global__ __launch_bounds__(1024) void pij_k(float* __restrict__ out2) {
  __shared__ float Ts[32][33];
  int b = blockIdx.z;
  int i0 = blockIdx.y*32, j0 = blockIdx.x*32;
  int tx = threadIdx.x, ty = threadIdx.y;
  const float* L = g_Li + (size_t)b*TT*TT;
  Ts[ty][tx] = L[(size_t)(j0+ty)*TT + i0 + tx];
  __syncthreads();
  int i = i0 + ty, j = j0 + tx;
  float av  = g_A[(size_t)b*TT*TT + (size_t)i*TT + j];
  float dj  = (j > 0) ? g_dg[b*TT + j] : 0.0f;
  float lji = (i > 0) ? Ts[tx][ty] : 0.0f;
  out2[(size_t)b*TT1*TT + (size_t)(i+1)*TT + j] = av * (dj - lji);
}

__global__ void addroot_k(const float* __restrict__ re, const float* __restrict__ out2) {
  int idx = blockIdx.x*blockDim.x + threadIdx.x;
  int c = idx & 255, bi = idx >> 8;
  int b = bi >> 9, i = bi & 511;
  float pr = out2[(size_t)b*TT1*TT + i];
  g_cat[(size_t)bi*HD + c] += pr * re[c];
}

// ---------------- tf32 tensor-core GEMM ----------------
#define TFA 136
#define TFB 72
__device__ __forceinline__ float f2tf(float f) {
  unsigned u; asm("cvt.rna.tf32.f32 %0, %1;" : "=r"(u) : "f"(f));
  return __uint_as_float(u);
}
__device__ __forceinline__ void mma_tf32(float* d, const unsigned* a, unsigned b0, unsigned b1) {
  asm volatile("mma.sync.aligned.m16n8k8.row.col.f32.tf32.tf32.f32 "
    "{%0,%1,%2,%3}, {%4,%5,%6,%7}, {%8,%9}, {%0,%1,%2,%3};"
    : "+f"(d[0]), "+f"(d[1]), "+f"(d[2]), "+f"(d[3])
    : "r"(a[0]), "r"(a[1]), "r"(a[2]), "r"(a[3]), "r"(b0), "r"(b1));
}
template<int MODE, bool SPLIT>
__global__ __launch_bounds__(256)
void tgemm_k(const float* __restrict__ A, int lda, long long sA,
             const float* __restrict__ B, int ldb, long long sB,
             float* __restrict__ C, int ldc, long long sC,
             int K, const float* __restrict__ bias, int act, const int* __restrict__ seq)
{
  __shared__ __align__(16) float As[16*TFA];
  __shared__ __align__(16) float Bs[16*TFB];
  int tid = threadIdx.x;
  int m0 = blockIdx.y*128, n0 = blockIdx.x*64;
  const float* Ab = A + (size_t)blockIdx.z*sA;
  const float* Bb = B + (size_t)blockIdx.z*sB;
  float* Cb = C + (size_t)blockIdx.z*sC;
  int warp = tid>>5, lane = tid&31;
  int wm = (warp&3)*32, wn = (warp>>2)*32;
  int g = lane>>2, la3 = lane&3;
  float acc[2][4][4];
#pragma unroll
  for(int a=0;a<2;a++)
#pragma unroll
    for(int b=0;b<4;b++)
#pragma unroll
      for(int c=0;c<4;c++) acc[a][b][c]=0.f;

  for (int k0 = 0; k0 < K; k0 += 16) {
    __syncthreads();
#pragma unroll
    for (int q = 0; q < 2; ++q) {
      int idx = tid + q*256;
      if (MODE == 2) {
        int kr = idx >> 5, c4 = (idx & 31)*4;
        float4 v = *(const float4*)(Ab + (size_t)(k0+kr)*lda + m0 + c4);
        if (!SPLIT) { v.x = f2tf(v.x); v.y = f2tf(v.y); v.z = f2tf(v.z); v.w = f2tf(v.w); }
        *(float4*)(As + kr*TFA + c4) = v;
      } else {
        int r = idx >> 2, c4 = (idx & 3)*4;
        float4 v = *(const float4*)(Ab + (size_t)(m0+r)*lda + k0 + c4);
        if (!SPLIT) { v.x = f2tf(v.x); v.y = f2tf(v.y); v.z = f2tf(v.z); v.w = f2tf(v.w); }
        As[(c4+0)*TFA + r] = v.x; As[(c4+1)*TFA + r] = v.y;
        As[(c4+2)*TFA + r] = v.z; As[(c4+3)*TFA + r] = v.w;
      }
    }
    {
      int idx = tid;
      if (MODE == 0) {
        int r = idx >> 2, c4 = (idx & 3)*4;
        float4 v = *(const float4*)(Bb + (size_t)(n0+r)*ldb + k0 + c4);
        if (!SPLIT) { v.x = f2tf(v.x); v.y = f2tf(v.y); v.z = f2tf(v.z); v.w = f2tf(v.w); }
        Bs[(c4+0)*TFB + r] = v.x; Bs[(c4+1)*TFB + r] = v.y;
        Bs[(c4+2)*TFB + r] = v.z; Bs[(c4+3)*TFB + r] = v.w;
      } else {
        int kr = idx >> 4, c4 = (idx & 15)*4;
        float4 v = *(const float4*)(Bb + (size_t)(k0+kr)*ldb + n0 + c4);
        if (!SPLIT) { v.x = f2tf(v.x); v.y = f2tf(v.y); v.z = f2tf(v.z); v.w = f2tf(v.w); }
        *(float4*)(Bs + kr*TFB + c4) = v;
      }
    }
    __syncthreads();
#pragma unroll
    for (int ks = 0; ks < 2; ++ks) {
      int kb = ks*8;
      unsigned ah[2][4], al[2][4];
#pragma unroll
      for (int mt = 0; mt < 2; ++mt) {
        const float* ap = As + (kb + la3)*TFA + wm + mt*16 + g;
        float f0 = ap[0], f1 = ap[8], f2 = ap[4*TFA], f3 = ap[4*TFA + 8];
        if (SPLIT) {
          float h0 = f2tf(f0), h1 = f2tf(f1), h2 = f2tf(f2), h3 = f2tf(f3);
          ah[mt][0] = __float_as_uint(h0); al[mt][0] = __float_as_uint(f2tf(f0 - h0));
          ah[mt][1] = __float_as_uint(h1); al[mt][1] = __float_as_uint(f2tf(f1 - h1));
          ah[mt][2] = __float_as_uint(h2); al[mt][2] = __float_as_uint(f2tf(f2 - h2));
          ah[mt][3] = __float_as_uint(h3); al[mt][3] = __float_as_uint(f2tf(f3 - h3));
        } else {
          ah[mt][0] = __float_as_uint(f0); ah[mt][1] = __float_as_uint(f1);
          ah[mt][2] = __float_as_uint(f2); ah[mt][3] = __float_as_uint(f3);
        }
      }
#pragma unroll
      for (int nt = 0; nt < 4; ++nt) {
        const float* bp = Bs + (kb + la3)*TFB + wn + nt*8 + g;
        float bf0 = bp[0], bf1 = bp[4*TFB];
        unsigned bh0, bh1, bl0, bl1;
        if (SPLIT) {
          float h0 = f2tf(bf0), h1 = f2tf(bf1);
          bh0 = __float_as_uint(h0); bl0 = __float_as_uint(f2tf(bf0 - h0));
          bh1 = __float_as_uint(h1); bl1 = __float_as_uint(f2tf(bf1 - h1));
        } else {
          bh0 = __float_as_uint(bf0); bh1 = __float_as_uint(bf1);
          bl0 = bl1 = 0;
        }
#pragma unroll
        for (int mt = 0; mt < 2; ++mt) {
          mma_tf32(acc[mt][nt], ah[mt], bh0, bh1);
          if (SPLIT) {
            mma_tf32(acc[mt][nt], ah[mt], bl0, bl1);
            mma_tf32(acc[mt][nt], al[mt], bh0, bh1);
          }
        }
      }
    }
  }
  int len = (act == 3) ? seq[blockIdx.z] : 0;
#pragma unroll
  for (int mt = 0; mt < 2; ++mt) {
    int mrow = m0 + wm + mt*16 + g;
#pragma unroll
    for (int nt = 0; nt < 4; ++nt) {
      int ncol = n0 + wn + nt*8 + la3*2;
      float b0v = 0.f, b1v = 0.f;
      if (bias) { b0v = bias[ncol]; b1v = bias[ncol+1]; }
      float v[4] = { acc[mt][nt][0] + b0v, acc[mt][nt][1] + b1v,
                     acc[mt][nt][2] + b0v, acc[mt][nt][3] + b1v };
      if (act == 1) {
        v[0]=tanhf(v[0]); v[1]=tanhf(v[1]); v[2]=tanhf(v[2]); v[3]=tanhf(v[3]);
      } else if (act == 2) {
#pragma unroll
        for (int q = 0; q < 4; ++q) v[q] = v[q]>=0.f ? v[q] : 0.01f*v[q];
      } else if (act == 3) {
#pragma unroll
        for (int q = 0; q < 4; ++q) {
          int gi = mrow + (q >= 2 ? 8 : 0);
          int gj = ncol + (q & 1);
          v[q] = (gi != gj && gi < len && gj < len) ? expf(v[q]) : 0.0f;
        }
      }
      *(float2*)(Cb + (size_t)mrow*ldc + ncol) = make_float2(v[0], v[1]);
      *(float2*)(Cb + (size_t)(mrow+8)*ldc + ncol) = make_float2(v[2], v[3]);
    }
  }
}

// ---------------- launch ----------------
extern "C" void kernel_launch(void* const* d_in, const int* in_sizes, int n_in,
                              void* d_out, int out_size) {
  (void)in_sizes; (void)n_in; (void)out_size;
  const float* x     = (const float*)d_in[0];
  const int*   seq   = (const int*)  d_in[1];
  const float* W_tp  = (const float*)d_in[2];
  const float* b_tp  = (const float*)d_in[3];
  const float* W_tc  = (const float*)d_in[4];
  const float* b_tc  = (const float*)d_in[5];
  const float* W_fij = (const float*)d_in[6];
  const float* w_root= (const float*)d_in[7];
  const float* r_emb = (const float*)d_in[8];
  const float* W_r   = (const float*)d_in[9];
  const float* b_r   = (const float*)d_in[10];
  const float* W_pc  = (const float*)d_in[11];
  const float* b_pc  = (const float*)d_in[12];
  float* out1 = (float*)d_out;
  float* out2 = out1 + (size_t)BT*SD;

  float *st,*se,*tp,*tc,*gg,*A,*L,*Li,*cat,*cat2,*Pb;
  int *srow;
  cudaGetSymbolAddress((void**)&st,   g_st);
  cudaGetSymbolAddress((void**)&se,   g_se);
  cudaGetSymbolAddress((void**)&tp,   g_tp);
  cudaGetSymbolAddress((void**)&tc,   g_tc);
  cudaGetSymbolAddress((void**)&gg,   g_gg);
  cudaGetSymbolAddress((void**)&A,    g_A);
  cudaGetSymbolAddress((void**)&L,    g_L);
  cudaGetSymbolAddress((void**)&Li,   g_Li);
  cudaGetSymbolAddress((void**)&cat,  g_cat);
  cudaGetSymbolAddress((void**)&cat2, g_cat2);
  cudaGetSymbolAddress((void**)&Pb,   g_P);
  cudaGetSymbolAddress((void**)&srow, g_srcrow);

  const int PANEL_SMEM  = TT*33*4;              // 67584
  const int UPDATE_SMEM = TT*33*4 + NB*132*4;   // 84480
  cudaFuncSetAttribute(panel_k,  cudaFuncAttributeMaxDynamicSharedMemorySize, PANEL_SMEM);
  cudaFuncSetAttribute(update_k, cudaFuncAttributeMaxDynamicSharedMemorySize, UPDATE_SMEM);

  cudaStream_t s2;
  cudaStreamCreateWithFlags(&s2, cudaStreamNonBlocking);
  cudaEvent_t evF, evP[16], evU[16];
  cudaEventCreateWithFlags(&evF, cudaEventDisableTiming);
  for (int i = 0; i < 16; ++i) {
    cudaEventCreateWithFlags(&evP[i], cudaEventDisableTiming);
    cudaEventCreateWithFlags(&evU[i], cudaEventDisableTiming);
  }

  const long long sTT = (long long)TT*TT, sTS = (long long)TT*SD,
                  sTH = (long long)TT*HD, sP = (long long)TT1*TT;
  const float* pij = out2 + TT;

  split_k<<<BT*HD/256, 256>>>(x);
  tgemm_k<0,true><<<dim3(4,128,1),256>>>(st, SD, 0, W_tp, SD, 0, tp, SD, 0, SD, b_tp, 1, 0);
  tgemm_k<0,true><<<dim3(4,128,1),256>>>(st, SD, 0, W_tc, SD, 0, tc, SD, 0, SD, b_tc, 1, 0);
  tgemm_k<1,true><<<dim3(4,128,1),256>>>(tp, SD, 0, W_fij, SD, 0, gg, SD, 0, SD, 0, 0, 0);
  tgemm_k<0,true><<<dim3(8,4,BB),256>>>(gg, SD, sTS, tc, SD, sTS, A, TT, sTT, SD, 0, 3, seq);
  root_k<<<BT*32/256, 256>>>(w_root, seq);
  zcs_k<<<BT/1024, 1024>>>();
  colsum_k<<<dim3(8,BB), 512>>>();
  buildL_k<<<MT/256, 256>>>(seq);

  // ---- overlapped blocked-GJ: P/Ucols chain on s2, Urest chain on default ----
  cudaEventRecord(evF, 0);
  cudaStreamWaitEvent(s2, evF, 0);
  for (int r = 0; r < TT/NB; ++r) {
    int k0 = r*NB;
    const float* sbuf = (r & 1) ? Li : L;
    float*       dbuf = (r & 1) ? L  : Li;
    float* pcur = Pb   + (size_t)(r & 1)*BB*TT*NB;
    int*   mcur = srow + (r & 1)*BT;
    panel_k<<<BB, 1024, PANEL_SMEM, s2>>>(sbuf, k0, pcur, mcur);
    cudaEventRecord(evP[r], s2);
    cudaStreamWaitEvent(0, evP[r], 0);
    int k0skip = (r < 15) ? k0 + NB : -1;
    update_k<<<dim3(4, BB), 1024, UPDATE_SMEM>>>(sbuf, dbuf, pcur, mcur, k0, k0skip, -1);
    cudaEventRecord(evU[r], 0);
    if (r < 15) {
      if (r >= 1) cudaStreamWaitEvent(s2, evU[r-1], 0);
      update_k<<<dim3(1, BB), 1024, UPDATE_SMEM, s2>>>(sbuf, dbuf, pcur, mcur, k0, -1, k0 + NB);
    }
  }
  // all s2 work joined via evP waits on the default stream

  gather_k<<<dim3(4, BB), 1024>>>();
  diag_k<<<BB, TT>>>(out2);
  pij_k<<<dim3(16,16,BB), dim3(32,32)>>>(out2);
  tgemm_k<2,false><<<dim3(4,4,BB),256>>>(pij, TT, sP, se, SD, sTS, cat, HD, sTH, TT, 0, 0, 0);
  addroot_k<<<MS/256, 256>>>(r_emb, out2);
  tgemm_k<1,false><<<dim3(4,4,BB),256>>>(pij, TT, sP, se, SD, sTS, cat + SD, HD, sTH, TT, 0, 0, 0);
  tgemm_k<0,false><<<dim3(4,128,1),256>>>(cat, HD, 0, W_r, HD, 0, cat2, HD, 0, HD, b_r, 2, 0);
  tgemm_k<1,false><<<dim3(4,4,BB),256>>>(pij, TT, sP, cat2, HD, sTH, cat2 + SD, HD, sTH, TT, 0, 0, 0);
  tgemm_k<0,false><<<dim3(4,128,1),256>>>(cat2, HD, 0, W_pc, HD, 0, out1, SD, 0, HD, b_pc, 2, 0);
}

// round 13
// speedup vs baseline: 1.2013x; 1.2013x over previous
#include <cuda_runtime.h>
#include <math.h>

#define BB 32
#define TT 512
#define TT1 513
#define SD 256
#define HD 512
#define BT (BB*TT)
#define MS (BT*SD)
#define MT (BT*TT)
#define NB 32

__device__ __align__(128) float g_st[MS], g_se[MS], g_tp[MS], g_tc[MS], g_gg[MS];
__device__ __align__(128) float g_A[MT], g_L[MT], g_Li[MT], g_cat[MT], g_cat2[MT];
__device__ __align__(128) float g_cs[BT], g_ar[BT], g_dg[BT];
__device__ __align__(128) int   g_piv[BT];
__device__ __align__(128) int   g_srcrow[BT];

// ---------------- elementwise ----------------
__global__ void split_k(const float* __restrict__ x) {
  int idx = blockIdx.x*blockDim.x + threadIdx.x;
  int c = idx & 511; int bt = idx >> 9;
  const float* xp = x + (size_t)bt*HD;
  if (c < SD) g_se[(size_t)bt*SD + c] = xp[c + ((c >= 128) ? 128 : 0)];
  else { int cc = c - SD; g_st[(size_t)bt*SD + cc] = xp[cc + 128 + ((cc >= 128) ? 128 : 0)]; }
}

__global__ void root_k(const float* __restrict__ wr, const int* __restrict__ seq) {
  int g = blockIdx.x*blockDim.x + threadIdx.x;
  int w = g >> 5, lane = g & 31;
  if (w >= BT) return;
  const float* s = g_st + (size_t)w*SD;
  float acc = 0.f;
  for (int c = lane; c < SD; c += 32) acc += s[c]*wr[c];
  for (int o = 16; o > 0; o >>= 1) acc += __shfl_down_sync(0xffffffffu, acc, o);
  if (lane == 0) {
    int b = w >> 9, t = w & 511;
    g_ar[w] = (t < seq[b]) ? expf(acc) : 0.0f;
  }
}

__global__ void zcs_k() {
  g_cs[blockIdx.x*1024 + threadIdx.x] = 0.0f;
}

__global__ void colsum_k() {
  int b = blockIdx.y, j = threadIdx.x;
  int i0 = blockIdx.x*64;
  const float* a = g_A + (size_t)b*TT*TT;
  float s = 0.f;
  #pragma unroll 8
  for (int i = i0; i < i0+64; ++i) s += a[(size_t)i*TT + j];
  atomicAdd(&g_cs[b*TT + j], s);
}

__global__ void buildL_k(const int* __restrict__ seq) {
  int idx = blockIdx.x*blockDim.x + threadIdx.x;
  int j = idx & 511, i = (idx >> 9) & 511, b = idx >> 18;
  float v;
  if (i == 0) v = g_ar[b*TT + j];
  else {
    v = -g_A[idx];
    if (i == j) v += g_cs[b*TT + j] + ((j >= seq[b]) ? 1.0f : 0.0f);
  }
  g_L[idx] = v;
}

// ---------------- blocked Gauss-Jordan inverse (NB=32, partial pivoting) ----------------
// Register-resident panel: thread (warp c, lane) owns column c, physical rows lane+32w.
// Row swaps are permutation bookkeeping (cur/logpos); pivot selection for step kk+1 is
// computed by warp kk+1 inside step kk's update phase. 2 barriers per pivot step.
__global__ __launch_bounds__(1024) void panel_k(const float* __restrict__ srcM,
                                                float* __restrict__ dstM, int k0) {
  extern __shared__ float stage[];        // 512 x 33
  __shared__ float colA[TT], colB[TT];
  __shared__ float rowk[NB];
  __shared__ int cur[TT], logpos[TT];
  __shared__ float sPinv; __shared__ int sPr;
  int b = blockIdx.x, tid = threadIdx.x;
  int c = tid >> 5, lane = tid & 31;
  const float* src = srcM + (size_t)b*TT*TT;
  float* dst = dstM + (size_t)b*TT*TT;
  for (int idx = tid; idx < TT*NB; idx += 1024) {
    int i = idx >> 5, cc = idx & 31;
    stage[i*33+cc] = src[(size_t)i*TT + k0 + cc];
  }
  if (tid < TT) { cur[tid] = tid; logpos[tid] = tid; }
  __syncthreads();
  float val[16];
#pragma unroll
  for (int w = 0; w < 16; ++w) val[w] = stage[(lane+32*w)*33 + c];
  // prologue: warp 0 publishes colA (column 0 multipliers) + selects pivot 0
  if (c == 0) {
    float bv = -1.f; int bp = lane; float bs = 0.f;
#pragma unroll
    for (int w = 0; w < 16; ++w) {
      int p = lane + 32*w;
      colA[p] = val[w];
      if (p >= k0) {
        float av = fabsf(val[w]);
        if (av > bv) { bv = av; bp = p; bs = val[w]; }
      }
    }
    for (int o = 16; o > 0; o >>= 1) {
      float v2 = __shfl_down_sync(0xffffffffu, bv, o);
      int   p2 = __shfl_down_sync(0xffffffffu, bp, o);
      float s2 = __shfl_down_sync(0xffffffffu, bs, o);
      if (v2 > bv) { bv = v2; bp = p2; bs = s2; }
    }
    if (lane == 0) {
      int lp = logpos[bp];
      int pk = cur[k0];
      cur[k0] = bp; cur[lp] = pk;
      logpos[bp] = k0; logpos[pk] = lp;
      g_piv[b*TT + k0] = lp;
      sPr = bp; sPinv = 1.0f / bs;
    }
  }
  for (int kk = 0; kk < NB; ++kk) {
    __syncthreads();               // perms + sPr/sPinv + colM buffer ready
    int pr = sPr; float pinv = sPinv;
    // A: pivot-row owners scale + publish rowk
#pragma unroll
    for (int w = 0; w < 16; ++w) {
      if (lane + 32*w == pr) {
        float v = (c == kk) ? 1.0f : val[w];
        v *= pinv;
        val[w] = v;
        rowk[c] = v;
      }
    }
    __syncthreads();
    // B: rank-1 update; warp kk+1 then selects next pivot + publishes its column
    float rk = rowk[c];
    const float* colR = (kk & 1) ? colB : colA;
#pragma unroll
    for (int w = 0; w < 16; ++w) {
      int p = lane + 32*w;
      if (p != pr) {
        float m = colR[p];
        float cv = (c == kk) ? 0.0f : val[w];
        val[w] = cv - m*rk;
      }
    }
    if (kk < NB-1 && c == kk+1) {
      float* colW = (kk & 1) ? colA : colB;
      int kn = k0 + kk + 1;
      float bv = -1.f; int bp = lane; float bs = 0.f;
#pragma unroll
      for (int w = 0; w < 16; ++w) {
        int p = lane + 32*w;
        colW[p] = val[w];
        if (logpos[p] >= kn) {
          float av = fabsf(val[w]);
          if (av > bv) { bv = av; bp = p; bs = val[w]; }
        }
      }
      for (int o = 16; o > 0; o >>= 1) {
        float v2 = __shfl_down_sync(0xffffffffu, bv, o);
        int   p2 = __shfl_down_sync(0xffffffffu, bp, o);
        float s2 = __shfl_down_sync(0xffffffffu, bs, o);
        if (v2 > bv) { bv = v2; bp = p2; bs = s2; }
      }
      __syncwarp();
      if (lane == 0) {
        int lp = logpos[bp];
        int pk = cur[kn];
        cur[kn] = bp; cur[lp] = pk;
        logpos[bp] = kn; logpos[pk] = lp;
        g_piv[b*TT + kn] = lp;
        sPr = bp; sPinv = 1.0f / bs;
      }
    }
  }
  // epilogue: place registers in logical order, write back + sigma
#pragma unroll
  for (int w = 0; w < 16; ++w) {
    int p = lane + 32*w;
    stage[logpos[p]*33 + c] = val[w];
  }
  if (tid < TT) g_srcrow[b*TT + tid] = cur[tid];
  __syncthreads();
  for (int idx = tid; idx < TT*NB; idx += 1024) {
    int i = idx >> 5, cc = idx & 31;
    dst[(size_t)i*TT + k0 + cc] = stage[i*33+cc];
  }
}

// update_k: DST[i][j] = [i not in blk]*SRC[sigma(i)][j] + P[i][:].R[:][j], j outside blk.
__global__ __launch_bounds__(1024) void update_k(const float* __restrict__ srcM,
                                                 float* __restrict__ dstM, int k0) {
  extern __shared__ float sm[];
  float* Ps = sm;           // 512 x 33
  float* Rs = sm + TT*33;   // 32 x 132
  __shared__ int smap[TT];
  int b = blockIdx.y, tid = threadIdx.x;
  int jbase = blockIdx.x * 128;
  const float* src = srcM + (size_t)b*TT*TT;
  float* dst = dstM + (size_t)b*TT*TT;
  if (tid < TT) smap[tid] = g_srcrow[b*TT + tid];
  __syncthreads();
  for (int idx = tid; idx < TT*NB; idx += 1024) {
    int i = idx >> 5, c = idx & 31;
    Ps[i*33+c] = dst[(size_t)i*TT + k0 + c];
  }
  for (int idx = tid; idx < NB*128; idx += 1024) {
    int k = idx >> 7, c = idx & 127;
    Rs[k*132+c] = src[(size_t)smap[k0+k]*TT + jbase + c];
  }
  __syncthreads();
  int tx = tid & 31, ty = tid >> 5;
  int j = jbase + tx*4;
  if (j >= k0 && j < k0 + NB) return;
  for (int r = 0; r < 4; ++r) {
    int i0 = r*128 + ty*4;
    float acc[4][4] = {};
#pragma unroll 8
    for (int k = 0; k < NB; ++k) {
      float4 rv = *(const float4*)(Rs + k*132 + tx*4);
      float p0 = Ps[(i0+0)*33+k], p1 = Ps[(i0+1)*33+k];
      float p2 = Ps[(i0+2)*33+k], p3 = Ps[(i0+3)*33+k];
      acc[0][0]+=p0*rv.x; acc[0][1]+=p0*rv.y; acc[0][2]+=p0*rv.z; acc[0][3]+=p0*rv.w;
      acc[1][0]+=p1*rv.x; acc[1][1]+=p1*rv.y; acc[1][2]+=p1*rv.z; acc[1][3]+=p1*rv.w;
      acc[2][0]+=p2*rv.x; acc[2][1]+=p2*rv.y; acc[2][2]+=p2*rv.z; acc[2][3]+=p2*rv.w;
      acc[3][0]+=p3*rv.x; acc[3][1]+=p3*rv.y; acc[3][2]+=p3*rv.z; acc[3][3]+=p3*rv.w;
    }
#pragma unroll
    for (int q = 0; q < 4; ++q) {
      int i = i0 + q;
      float4 res;
      if (i >= k0 && i < k0 + NB) res = make_float4(0.f,0.f,0.f,0.f);
      else res = *(const float4*)(src + (size_t)smap[i]*TT + j);
      res.x += acc[q][0]; res.y += acc[q][1]; res.z += acc[q][2]; res.w += acc[q][3];
      *(float4*)(dst + (size_t)i*TT + j) = res;
    }
  }
}

__global__ __launch_bounds__(1024) void gather_k() {
  __shared__ int arr[TT];
  int b = blockIdx.y, tid = threadIdx.x;
  if (tid == 0) {
    for (int j = 0; j < TT; ++j) arr[j] = j;
    for (int l = TT-1; l >= 0; --l) {
      int p = g_piv[b*TT + l];
      if (p != l) { int t = arr[l]; arr[l] = arr[p]; arr[p] = t; }
    }
  }
  __syncthreads();
  const float* a = g_L + (size_t)b*TT*TT;
  float* o = g_Li + (size_t)b*TT*TT;
  int base = blockIdx.x * 128 * TT;
  for (int idx = tid; idx < 128*TT; idx += 1024) {
    int i = idx >> 9, j = idx & 511;
    o[base + idx] = a[(size_t)(blockIdx.x*128 + i)*TT + arr[j]];
  }
}

__global__ void diag_k(float* __restrict__ out2) {
  int b = blockIdx.x, j = threadIdx.x;
  const float* L = g_Li + (size_t)b*TT*TT;
  g_dg[b*TT + j] = L[(size_t)j*TT + j];
  out2[(size_t)b*TT1*TT + j] = g_ar[b*TT + j] * L[(size_t)j*TT];
}

__global__ __launch_bounds__(1024) void pij_k(float* __restrict__ out2) {
  __shared__ float Ts[32][33];
  int b = blockIdx.z;
  int i0 = blockIdx.y*32, j0 = blockIdx.x*32;
  int tx = threadIdx.x, ty = threadIdx.y;
  const float* L = g_Li + (size_t)b*TT*TT;
  Ts[ty][tx] = L[(size_t)(j0+ty)*TT + i0 + tx];
  __syncthreads();
  int i = i0 + ty, j = j0 + tx;
  float av  = g_A[(size_t)b*TT*TT + (size_t)i*TT + j];
  float dj  = (j > 0) ? g_dg[b*TT + j] : 0.0f;
  float lji = (i > 0) ? Ts[tx][ty] : 0.0f;
  out2[(size_t)b*TT1*TT + (size_t)(i+1)*TT + j] = av * (dj - lji);
}

// ---------------- tf32 tensor-core GEMM ----------------
// act: 0 none, 1 tanh, 2 leaky, 3 exp+mask, 4 add p_root*root_emb (aux=out2 slab, bias=root_emb)
#define TFA 136
#define TFB 72
__device__ __forceinline__ float f2tf(float f) {
  unsigned u; asm("cvt.rna.tf32.f32 %0, %1;" : "=r"(u) : "f"(f));
  return __uint_as_float(u);
}
__device__ __forceinline__ void mma_tf32(float* d, const unsigned* a, unsigned b0, unsigned b1) {
  asm volatile("mma.sync.aligned.m16n8k8.row.col.f32.tf32.tf32.f32 "
    "{%0,%1,%2,%3}, {%4,%5,%6,%7}, {%8,%9}, {%0,%1,%2,%3};"
    : "+f"(d[0]), "+f"(d[1]), "+f"(d[2]), "+f"(d[3])
    : "r"(a[0]), "r"(a[1]), "r"(a[2]), "r"(a[3]), "r"(b0), "r"(b1));
}
template<int MODE, bool SPLIT>
__global__ __launch_bounds__(256)
void tgemm_k(const float* __restrict__ A, int lda, long long sA,
             const float* __restrict__ B, int ldb, long long sB,
             float* __restrict__ C, int ldc, long long sC,
             int K, const float* __restrict__ bias, int act, const int* __restrict__ seq,
             const float* __restrict__ aux)
{
  __shared__ __align__(16) float As[16*TFA];
  __shared__ __align__(16) float Bs[16*TFB];
  int tid = threadIdx.x;
  int m0 = blockIdx.y*128, n0 = blockIdx.x*64;
  const float* Ab = A + (size_t)blockIdx.z*sA;
  const float* Bb = B + (size_t)blockIdx.z*sB;
  float* Cb = C + (size_t)blockIdx.z*sC;
  int warp = tid>>5, lane = tid&31;
  int wm = (warp&3)*32, wn = (warp>>2)*32;
  int g = lane>>2, la3 = lane&3;
  float acc[2][4][4];
#pragma unroll
  for(int a=0;a<2;a++)
#pragma unroll
    for(int b=0;b<4;b++)
#pragma unroll
      for(int c=0;c<4;c++) acc[a][b][c]=0.f;

  for (int k0 = 0; k0 < K; k0 += 16) {
    __syncthreads();
#pragma unroll
    for (int q = 0; q < 2; ++q) {
      int idx = tid + q*256;
      if (MODE == 2) {
        int kr = idx >> 5, c4 = (idx & 31)*4;
        float4 v = *(const float4*)(Ab + (size_t)(k0+kr)*lda + m0 + c4);
        if (!SPLIT) { v.x = f2tf(v.x); v.y = f2tf(v.y); v.z = f2tf(v.z); v.w = f2tf(v.w); }
        *(float4*)(As + kr*TFA + c4) = v;
      } else {
        int r = idx >> 2, c4 = (idx & 3)*4;
        float4 v = *(const float4*)(Ab + (size_t)(m0+r)*lda + k0 + c4);
        if (!SPLIT) { v.x = f2tf(v.x); v.y = f2tf(v.y); v.z = f2tf(v.z); v.w = f2tf(v.w); }
        As[(c4+0)*TFA + r] = v.x; As[(c4+1)*TFA + r] = v.y;
        As[(c4+2)*TFA + r] = v.z; As[(c4+3)*TFA + r] = v.w;
      }
    }
    {
      int idx = tid;
      if (MODE == 0) {
        int r = idx >> 2, c4 = (idx & 3)*4;
        float4 v = *(const float4*)(Bb + (size_t)(n0+r)*ldb + k0 + c4);
        if (!SPLIT) { v.x = f2tf(v.x); v.y = f2tf(v.y); v.z = f2tf(v.z); v.w = f2tf(v.w); }
        Bs[(c4+0)*TFB + r] = v.x; Bs[(c4+1)*TFB + r] = v.y;
        Bs[(c4+2)*TFB + r] = v.z; Bs[(c4+3)*TFB + r] = v.w;
      } else {
        int kr = idx >> 4, c4 = (idx & 15)*4;
        float4 v = *(const float4*)(Bb + (size_t)(k0+kr)*ldb + n0 + c4);
        if (!SPLIT) { v.x = f2tf(v.x); v.y = f2tf(v.y); v.z = f2tf(v.z); v.w = f2tf(v.w); }
        *(float4*)(Bs + kr*TFB + c4) = v;
      }
    }
    __syncthreads();
#pragma unroll
    for (int ks = 0; ks < 2; ++ks) {
      int kb = ks*8;
      unsigned ah[2][4], al[2][4];
#pragma unroll
      for (int mt = 0; mt < 2; ++mt) {
        const float* ap = As + (kb + la3)*TFA + wm + mt*16 + g;
        float f0 = ap[0], f1 = ap[8], f2 = ap[4*TFA], f3 = ap[4*TFA + 8];
        if (SPLIT) {
          float h0 = f2tf(f0), h1 = f2tf(f1), h2 = f2tf(f2), h3 = f2tf(f3);
          ah[mt][0] = __float_as_uint(h0); al[mt][0] = __float_as_uint(f2tf(f0 - h0));
          ah[mt][1] = __float_as_uint(h1); al[mt][1] = __float_as_uint(f2tf(f1 - h1));
          ah[mt][2] = __float_as_uint(h2); al[mt][2] = __float_as_uint(f2tf(f2 - h2));
          ah[mt][3] = __float_as_uint(h3); al[mt][3] = __float_as_uint(f2tf(f3 - h3));
        } else {
          ah[mt][0] = __float_as_uint(f0); ah[mt][1] = __float_as_uint(f1);
          ah[mt][2] = __float_as_uint(f2); ah[mt][3] = __float_as_uint(f3);
        }
      }
#pragma unroll
      for (int nt = 0; nt < 4; ++nt) {
        const float* bp = Bs + (kb + la3)*TFB + wn + nt*8 + g;
        float bf0 = bp[0], bf1 = bp[4*TFB];
        unsigned bh0, bh1, bl0, bl1;
        if (SPLIT) {
          float h0 = f2tf(bf0), h1 = f2tf(bf1);
          bh0 = __float_as_uint(h0); bl0 = __float_as_uint(f2tf(bf0 - h0));
          bh1 = __float_as_uint(h1); bl1 = __float_as_uint(f2tf(bf1 - h1));
        } else {
          bh0 = __float_as_uint(bf0); bh1 = __float_as_uint(bf1);
          bl0 = bl1 = 0;
        }
#pragma unroll
        for (int mt = 0; mt < 2; ++mt) {
          mma_tf32(acc[mt][nt], ah[mt], bh0, bh1);
          if (SPLIT) {
            mma_tf32(acc[mt][nt], ah[mt], bl0, bl1);
            mma_tf32(acc[mt][nt], al[mt], bh0, bh1);
          }
        }
      }
    }
  }
  int len = (act == 3) ? seq[blockIdx.z] : 0;
#pragma unroll
  for (int mt = 0; mt < 2; ++mt) {
    int mrow = m0 + wm + mt*16 + g;
#pragma unroll
    for (int nt = 0; nt < 4; ++nt) {
      int ncol = n0 + wn + nt*8 + la3*2;
      float b0v = 0.f, b1v = 0.f;
      if (bias && act != 4) { b0v = bias[ncol]; b1v = bias[ncol+1]; }
      float v[4] = { acc[mt][nt][0] + b0v, acc[mt][nt][1] + b1v,
                     acc[mt][nt][2] + b0v, acc[mt][nt][3] + b1v };
      if (act == 1) {
        v[0]=tanhf(v[0]); v[1]=tanhf(v[1]); v[2]=tanhf(v[2]); v[3]=tanhf(v[3]);
      } else if (act == 2) {
#pragma unroll
        for (int q = 0; q < 4; ++q) v[q] = v[q]>=0.f ? v[q] : 0.01f*v[q];
      } else if (act == 3) {
#pragma unroll
        for (int q = 0; q < 4; ++q) {
          int gi = mrow + (q >= 2 ? 8 : 0);
          int gj = ncol + (q & 1);
          v[q] = (gi != gj && gi < len && gj < len) ? expf(v[q]) : 0.0f;
        }
      } else if (act == 4) {
        float pr0 = aux[(size_t)blockIdx.z*TT1*TT + mrow];
        float pr8 = aux[(size_t)blockIdx.z*TT1*TT + mrow + 8];
        v[0] += pr0*bias[ncol]; v[1] += pr0*bias[ncol+1];
        v[2] += pr8*bias[ncol]; v[3] += pr8*bias[ncol+1];
      }
      *(float2*)(Cb + (size_t)mrow*ldc + ncol) = make_float2(v[0], v[1]);
      *(float2*)(Cb + (size_t)(mrow+8)*ldc + ncol) = make_float2(v[2], v[3]);
    }
  }
}

// ---------------- launch ----------------
extern "C" void kernel_launch(void* const* d_in, const int* in_sizes, int n_in,
                              void* d_out, int out_size) {
  (void)in_sizes; (void)n_in; (void)out_size;
  const float* x     = (const float*)d_in[0];
  const int*   seq   = (const int*)  d_in[1];
  const float* W_tp  = (const float*)d_in[2];
  const float* b_tp  = (const float*)d_in[3];
  const float* W_tc  = (const float*)d_in[4];
  const float* b_tc  = (const float*)d_in[5];
  const float* W_fij = (const float*)d_in[6];
  const float* w_root= (const float*)d_in[7];
  const float* r_emb = (const float*)d_in[8];
  const float* W_r   = (const float*)d_in[9];
  const float* b_r   = (const float*)d_in[10];
  const float* W_pc  = (const float*)d_in[11];
  const float* b_pc  = (const float*)d_in[12];
  float* out1 = (float*)d_out;
  float* out2 = out1 + (size_t)BT*SD;

  float *st,*se,*tp,*tc,*gg,*A,*L,*Li,*cat,*cat2;
  cudaGetSymbolAddress((void**)&st,   g_st);
  cudaGetSymbolAddress((void**)&se,   g_se);
  cudaGetSymbolAddress((void**)&tp,   g_tp);
  cudaGetSymbolAddress((void**)&tc,   g_tc);
  cudaGetSymbolAddress((void**)&gg,   g_gg);
  cudaGetSymbolAddress((void**)&A,    g_A);
  cudaGetSymbolAddress((void**)&L,    g_L);
  cudaGetSymbolAddress((void**)&Li,   g_Li);
  cudaGetSymbolAddress((void**)&cat,  g_cat);
  cudaGetSymbolAddress((void**)&cat2, g_cat2);

  const int PANEL_SMEM  = TT*33*4;              // 67584
  const int UPDATE_SMEM = TT*33*4 + NB*132*4;   // 84480
  cudaFuncSetAttribute(panel_k,  cudaFuncAttributeMaxDynamicSharedMemorySize, PANEL_SMEM);
  cudaFuncSetAttribute(update_k, cudaFuncAttributeMaxDynamicSharedMemorySize, UPDATE_SMEM);

  const long long sTT = (long long)TT*TT, sTS = (long long)TT*SD,
                  sTH = (long long)TT*HD, sP = (long long)TT1*TT;
  const float* pij = out2 + TT;

  split_k<<<BT*HD/256, 256>>>(x);
  tgemm_k<0,true><<<dim3(4,128,1),256>>>(st, SD, 0, W_tp, SD, 0, tp, SD, 0, SD, b_tp, 1, 0, 0);
  tgemm_k<0,true><<<dim3(4,128,1),256>>>(st, SD, 0, W_tc, SD, 0, tc, SD, 0, SD, b_tc, 1, 0, 0);
  tgemm_k<1,true><<<dim3(4,128,1),256>>>(tp, SD, 0, W_fij, SD, 0, gg, SD, 0, SD, 0, 0, 0, 0);
  tgemm_k<0,true><<<dim3(8,4,BB),256>>>(gg, SD, sTS, tc, SD, sTS, A, TT, sTT, SD, 0, 3, seq, 0);
  root_k<<<BT*32/256, 256>>>(w_root, seq);
  zcs_k<<<BT/1024, 1024>>>();
  colsum_k<<<dim3(8,BB), 512>>>();
  buildL_k<<<MT/256, 256>>>(seq);
  for (int kb = 0; kb < TT/NB; ++kb) {
    const float* s_ = (kb & 1) ? Li : L;
    float*       d_ = (kb & 1) ? L  : Li;
    panel_k<<<BB, 1024, PANEL_SMEM>>>(s_, d_, kb*NB);
    update_k<<<dim3(4, BB), 1024, UPDATE_SMEM>>>(s_, d_, kb*NB);
  }
  gather_k<<<dim3(4, BB), 1024>>>();
  diag_k<<<BB, TT>>>(out2);
  pij_k<<<dim3(16,16,BB), dim3(32,32)>>>(out2);
  // parents + fused root contribution
  tgemm_k<2,false><<<dim3(4,4,BB),256>>>(pij, TT, sP, se, SD, sTS, cat, HD, sTH, TT, r_emb, 4, 0, out2);
  tgemm_k<1,false><<<dim3(4,4,BB),256>>>(pij, TT, sP, se, SD, sTS, cat + SD, HD, sTH, TT, 0, 0, 0, 0);
  tgemm_k<0,false><<<dim3(4,128,1),256>>>(cat, HD, 0, W_r, HD, 0, cat2, HD, 0, HD, b_r, 2, 0, 0);
  tgemm_k<1,false><<<dim3(4,4,BB),256>>>(pij, TT, sP, cat2, HD, sTH, cat2 + SD, HD, sTH, TT, 0, 0, 0, 0);
  tgemm_k<0,false><<<dim3(4,128,1),256>>>(cat2, HD, 0, W_pc, HD, 0, out1, SD, 0, HD, b_pc, 2, 0, 0);
}

// round 14
// speedup vs baseline: 1.2031x; 1.0015x over previous
#include <cuda_runtime.h>
#include <math.h>

#define BB 32
#define TT 512
#define TT1 513
#define SD 256
#define HD 512
#define BT (BB*TT)
#define MS (BT*SD)
#define MT (BT*TT)
#define NB 32

__device__ __align__(128) float g_st[MS], g_se[MS], g_tp[MS], g_tc[MS], g_gg[MS];
__device__ __align__(128) float g_A[MT], g_L[MT], g_Li[MT], g_cat[MT], g_cat2[MT];
__device__ __align__(128) float g_cs[BT], g_ar[BT], g_dg[BT];
__device__ __align__(128) int   g_piv[BT];
__device__ __align__(128) int   g_srcrow[BT];

// ---------------- elementwise ----------------
__global__ void split_k(const float* __restrict__ x) {
  int idx = blockIdx.x*blockDim.x + threadIdx.x;
  int c = idx & 511; int bt = idx >> 9;
  const float* xp = x + (size_t)bt*HD;
  if (c < SD) g_se[(size_t)bt*SD + c] = xp[c + ((c >= 128) ? 128 : 0)];
  else { int cc = c - SD; g_st[(size_t)bt*SD + cc] = xp[cc + 128 + ((cc >= 128) ? 128 : 0)]; }
}

__global__ void root_k(const float* __restrict__ wr, const int* __restrict__ seq) {
  int g = blockIdx.x*blockDim.x + threadIdx.x;
  int w = g >> 5, lane = g & 31;
  if (w >= BT) return;
  const float* s = g_st + (size_t)w*SD;
  float acc = 0.f;
  for (int c = lane; c < SD; c += 32) acc += s[c]*wr[c];
  for (int o = 16; o > 0; o >>= 1) acc += __shfl_down_sync(0xffffffffu, acc, o);
  if (lane == 0) {
    int b = w >> 9, t = w & 511;
    g_ar[w] = (t < seq[b]) ? expf(acc) : 0.0f;
  }
}

__global__ void zcs_k() {
  g_cs[blockIdx.x*1024 + threadIdx.x] = 0.0f;
}

__global__ void colsum_k() {
  int b = blockIdx.y, j = threadIdx.x;
  int i0 = blockIdx.x*64;
  const float* a = g_A + (size_t)b*TT*TT;
  float s = 0.f;
  #pragma unroll 8
  for (int i = i0; i < i0+64; ++i) s += a[(size_t)i*TT + j];
  atomicAdd(&g_cs[b*TT + j], s);
}

__global__ void buildL_k(const int* __restrict__ seq) {
  int idx = blockIdx.x*blockDim.x + threadIdx.x;
  int j = idx & 511, i = (idx >> 9) & 511, b = idx >> 18;
  float v;
  if (i == 0) v = g_ar[b*TT + j];
  else {
    v = -g_A[idx];
    if (i == j) v += g_cs[b*TT + j] + ((j >= seq[b]) ? 1.0f : 0.0f);
  }
  g_L[idx] = v;
}

// ---------------- blocked Gauss-Jordan inverse (NB=32, partial pivoting) ----------------
// Register-resident panel; 2 barriers per pivot step (see R13).
__global__ __launch_bounds__(1024) void panel_k(const float* __restrict__ srcM,
                                                float* __restrict__ dstM, int k0) {
  extern __shared__ float stage[];        // 512 x 33
  __shared__ float colA[TT], colB[TT];
  __shared__ float rowk[NB];
  __shared__ int cur[TT], logpos[TT];
  __shared__ float sPinv; __shared__ int sPr;
  int b = blockIdx.x, tid = threadIdx.x;
  int c = tid >> 5, lane = tid & 31;
  const float* src = srcM + (size_t)b*TT*TT;
  float* dst = dstM + (size_t)b*TT*TT;
  for (int idx = tid; idx < TT*NB; idx += 1024) {
    int i = idx >> 5, cc = idx & 31;
    stage[i*33+cc] = src[(size_t)i*TT + k0 + cc];
  }
  if (tid < TT) { cur[tid] = tid; logpos[tid] = tid; }
  __syncthreads();
  float val[16];
#pragma unroll
  for (int w = 0; w < 16; ++w) val[w] = stage[(lane+32*w)*33 + c];
  if (c == 0) {
    float bv = -1.f; int bp = lane; float bs = 0.f;
#pragma unroll
    for (int w = 0; w < 16; ++w) {
      int p = lane + 32*w;
      colA[p] = val[w];
      if (p >= k0) {
        float av = fabsf(val[w]);
        if (av > bv) { bv = av; bp = p; bs = val[w]; }
      }
    }
    for (int o = 16; o > 0; o >>= 1) {
      float v2 = __shfl_down_sync(0xffffffffu, bv, o);
      int   p2 = __shfl_down_sync(0xffffffffu, bp, o);
      float s2 = __shfl_down_sync(0xffffffffu, bs, o);
      if (v2 > bv) { bv = v2; bp = p2; bs = s2; }
    }
    if (lane == 0) {
      int lp = logpos[bp];
      int pk = cur[k0];
      cur[k0] = bp; cur[lp] = pk;
      logpos[bp] = k0; logpos[pk] = lp;
      g_piv[b*TT + k0] = lp;
      sPr = bp; sPinv = 1.0f / bs;
    }
  }
  for (int kk = 0; kk < NB; ++kk) {
    __syncthreads();
    int pr = sPr; float pinv = sPinv;
#pragma unroll
    for (int w = 0; w < 16; ++w) {
      if (lane + 32*w == pr) {
        float v = (c == kk) ? 1.0f : val[w];
        v *= pinv;
        val[w] = v;
        rowk[c] = v;
      }
    }
    __syncthreads();
    float rk = rowk[c];
    const float* colR = (kk & 1) ? colB : colA;
#pragma unroll
    for (int w = 0; w < 16; ++w) {
      int p = lane + 32*w;
      if (p != pr) {
        float m = colR[p];
        float cv = (c == kk) ? 0.0f : val[w];
        val[w] = cv - m*rk;
      }
    }
    if (kk < NB-1 && c == kk+1) {
      float* colW = (kk & 1) ? colA : colB;
      int kn = k0 + kk + 1;
      float bv = -1.f; int bp = lane; float bs = 0.f;
#pragma unroll
      for (int w = 0; w < 16; ++w) {
        int p = lane + 32*w;
        colW[p] = val[w];
        if (logpos[p] >= kn) {
          float av = fabsf(val[w]);
          if (av > bv) { bv = av; bp = p; bs = val[w]; }
        }
      }
      for (int o = 16; o > 0; o >>= 1) {
        float v2 = __shfl_down_sync(0xffffffffu, bv, o);
        int   p2 = __shfl_down_sync(0xffffffffu, bp, o);
        float s2 = __shfl_down_sync(0xffffffffu, bs, o);
        if (v2 > bv) { bv = v2; bp = p2; bs = s2; }
      }
      __syncwarp();
      if (lane == 0) {
        int lp = logpos[bp];
        int pk = cur[kn];
        cur[kn] = bp; cur[lp] = pk;
        logpos[bp] = kn; logpos[pk] = lp;
        g_piv[b*TT + kn] = lp;
        sPr = bp; sPinv = 1.0f / bs;
      }
    }
  }
#pragma unroll
  for (int w = 0; w < 16; ++w) {
    int p = lane + 32*w;
    stage[logpos[p]*33 + c] = val[w];
  }
  if (tid < TT) g_srcrow[b*TT + tid] = cur[tid];
  __syncthreads();
  for (int idx = tid; idx < TT*NB; idx += 1024) {
    int i = idx >> 5, cc = idx & 31;
    dst[(size_t)i*TT + k0 + cc] = stage[i*33+cc];
  }
}

__global__ __launch_bounds__(1024) void update_k(const float* __restrict__ srcM,
                                                 float* __restrict__ dstM, int k0) {
  extern __shared__ float sm[];
  float* Ps = sm;           // 512 x 33
  float* Rs = sm + TT*33;   // 32 x 132
  __shared__ int smap[TT];
  int b = blockIdx.y, tid = threadIdx.x;
  int jbase = blockIdx.x * 128;
  const float* src = srcM + (size_t)b*TT*TT;
  float* dst = dstM + (size_t)b*TT*TT;
  if (tid < TT) smap[tid] = g_srcrow[b*TT + tid];
  __syncthreads();
  for (int idx = tid; idx < TT*NB; idx += 1024) {
    int i = idx >> 5, c = idx & 31;
    Ps[i*33+c] = dst[(size_t)i*TT + k0 + c];
  }
  for (int idx = tid; idx < NB*128; idx += 1024) {
    int k = idx >> 7, c = idx & 127;
    Rs[k*132+c] = src[(size_t)smap[k0+k]*TT + jbase + c];
  }
  __syncthreads();
  int tx = tid & 31, ty = tid >> 5;
  int j = jbase + tx*4;
  if (j >= k0 && j < k0 + NB) return;
  for (int r = 0; r < 4; ++r) {
    int i0 = r*128 + ty*4;
    float acc[4][4] = {};
#pragma unroll 8
    for (int k = 0; k < NB; ++k) {
      float4 rv = *(const float4*)(Rs + k*132 + tx*4);
      float p0 = Ps[(i0+0)*33+k], p1 = Ps[(i0+1)*33+k];
      float p2 = Ps[(i0+2)*33+k], p3 = Ps[(i0+3)*33+k];
      acc[0][0]+=p0*rv.x; acc[0][1]+=p0*rv.y; acc[0][2]+=p0*rv.z; acc[0][3]+=p0*rv.w;
      acc[1][0]+=p1*rv.x; acc[1][1]+=p1*rv.y; acc[1][2]+=p1*rv.z; acc[1][3]+=p1*rv.w;
      acc[2][0]+=p2*rv.x; acc[2][1]+=p2*rv.y; acc[2][2]+=p2*rv.z; acc[2][3]+=p2*rv.w;
      acc[3][0]+=p3*rv.x; acc[3][1]+=p3*rv.y; acc[3][2]+=p3*rv.z; acc[3][3]+=p3*rv.w;
    }
#pragma unroll
    for (int q = 0; q < 4; ++q) {
      int i = i0 + q;
      float4 res;
      if (i >= k0 && i < k0 + NB) res = make_float4(0.f,0.f,0.f,0.f);
      else res = *(const float4*)(src + (size_t)smap[i]*TT + j);
      res.x += acc[q][0]; res.y += acc[q][1]; res.z += acc[q][2]; res.w += acc[q][3];
      *(float4*)(dst + (size_t)i*TT + j) = res;
    }
  }
}

__global__ __launch_bounds__(1024) void gather_k() {
  __shared__ int arr[TT];
  int b = blockIdx.y, tid = threadIdx.x;
  if (tid == 0) {
    for (int j = 0; j < TT; ++j) arr[j] = j;
    for (int l = TT-1; l >= 0; --l) {
      int p = g_piv[b*TT + l];
      if (p != l) { int t = arr[l]; arr[l] = arr[p]; arr[p] = t; }
    }
  }
  __syncthreads();
  const float* a = g_L + (size_t)b*TT*TT;
  float* o = g_Li + (size_t)b*TT*TT;
  int base = blockIdx.x * 128 * TT;
  for (int idx = tid; idx < 128*TT; idx += 1024) {
    int i = idx >> 9, j = idx & 511;
    o[base + idx] = a[(size_t)(blockIdx.x*128 + i)*TT + arr[j]];
  }
}

__global__ void diag_k(float* __restrict__ out2) {
  int b = blockIdx.x, j = threadIdx.x;
  const float* L = g_Li + (size_t)b*TT*TT;
  g_dg[b*TT + j] = L[(size_t)j*TT + j];
  out2[(size_t)b*TT1*TT + j] = g_ar[b*TT + j] * L[(size_t)j*TT];
}

__global__ __launch_bounds__(1024) void pij_k(float* __restrict__ out2) {
  __shared__ float Ts[32][33];
  int b = blockIdx.z;
  int i0 = blockIdx.y*32, j0 = blockIdx.x*32;
  int tx = threadIdx.x, ty = threadIdx.y;
  const float* L = g_Li + (size_t)b*TT*TT;
  Ts[ty][tx] = L[(size_t)(j0+ty)*TT + i0 + tx];
  __syncthreads();
  int i = i0 + ty, j = j0 + tx;
  float av  = g_A[(size_t)b*TT*TT + (size_t)i*TT + j];
  float dj  = (j > 0) ? g_dg[b*TT + j] : 0.0f;
  float lji = (i > 0) ? Ts[tx][ty] : 0.0f;
  out2[(size_t)b*TT1*TT + (size_t)(i+1)*TT + j] = av * (dj - lji);
}

// ---------------- tf32 tensor-core GEMM (double-buffered pipeline) ----------------
// act: 0 none, 1 tanh, 2 leaky, 3 exp+mask, 4 add p_root*root_emb (aux=out2 slab, bias=root_emb)
#define TFA 136
#define TFB 72
__device__ __forceinline__ float f2tf(float f) {
  unsigned u; asm("cvt.rna.tf32.f32 %0, %1;" : "=r"(u) : "f"(f));
  return __uint_as_float(u);
}
__device__ __forceinline__ void mma_tf32(float* d, const unsigned* a, unsigned b0, unsigned b1) {
  asm volatile("mma.sync.aligned.m16n8k8.row.col.f32.tf32.tf32.f32 "
    "{%0,%1,%2,%3}, {%4,%5,%6,%7}, {%8,%9}, {%0,%1,%2,%3};"
    : "+f"(d[0]), "+f"(d[1]), "+f"(d[2]), "+f"(d[3])
    : "r"(a[0]), "r"(a[1]), "r"(a[2]), "r"(a[3]), "r"(b0), "r"(b1));
}
template<int MODE, bool SPLIT>
__global__ __launch_bounds__(256)
void tgemm_k(const float* __restrict__ A, int lda, long long sA,
             const float* __restrict__ B, int ldb, long long sB,
             float* __restrict__ C, int ldc, long long sC,
             int K, const float* __restrict__ bias, int act, const int* __restrict__ seq,
             const float* __restrict__ aux)
{
  __shared__ __align__(16) float As[2][16*TFA];
  __shared__ __align__(16) float Bs[2][16*TFB];
  int tid = threadIdx.x;
  int m0 = blockIdx.y*128, n0 = blockIdx.x*64;
  const float* Ab = A + (size_t)blockIdx.z*sA;
  const float* Bb = B + (size_t)blockIdx.z*sB;
  float* Cb = C + (size_t)blockIdx.z*sC;
  int warp = tid>>5, lane = tid&31;
  int wm = (warp&3)*32, wn = (warp>>2)*32;
  int g = lane>>2, la3 = lane&3;
  float acc[2][4][4];
#pragma unroll
  for(int a=0;a<2;a++)
#pragma unroll
    for(int b=0;b<4;b++)
#pragma unroll
      for(int c=0;c<4;c++) acc[a][b][c]=0.f;

  const int NT = K >> 4;
  float4 va0, va1, vb;

  // ---- tile load (gmem -> regs) ----
#define TG_LOAD(k0) do { \
    if (MODE == 2) { \
      int kr0 = tid >> 5, c40 = (tid & 31)*4; \
      va0 = *(const float4*)(Ab + (size_t)((k0)+kr0)*lda + m0 + c40); \
      int i1 = tid + 256; int kr1 = i1 >> 5, c41 = (i1 & 31)*4; \
      va1 = *(const float4*)(Ab + (size_t)((k0)+kr1)*lda + m0 + c41); \
    } else { \
      int r0 = tid >> 2, c40 = (tid & 3)*4; \
      va0 = *(const float4*)(Ab + (size_t)(m0+r0)*lda + (k0) + c40); \
      int i1 = tid + 256; int r1 = i1 >> 2, c41 = (i1 & 3)*4; \
      va1 = *(const float4*)(Ab + (size_t)(m0+r1)*lda + (k0) + c41); \
    } \
    if (MODE == 0) { \
      int r = tid >> 2, c4 = (tid & 3)*4; \
      vb = *(const float4*)(Bb + (size_t)(n0+r)*ldb + (k0) + c4); \
    } else { \
      int kr = tid >> 4, c4 = (tid & 15)*4; \
      vb = *(const float4*)(Bb + (size_t)((k0)+kr)*ldb + n0 + c4); \
    } \
  } while (0)

  // ---- tile store (regs -> smem stage s) ----
#define TG_STORE(s) do { \
    float4 w0 = va0, w1 = va1, wb = vb; \
    if (!SPLIT) { \
      w0.x = f2tf(w0.x); w0.y = f2tf(w0.y); w0.z = f2tf(w0.z); w0.w = f2tf(w0.w); \
      w1.x = f2tf(w1.x); w1.y = f2tf(w1.y); w1.z = f2tf(w1.z); w1.w = f2tf(w1.w); \
      wb.x = f2tf(wb.x); wb.y = f2tf(wb.y); wb.z = f2tf(wb.z); wb.w = f2tf(wb.w); \
    } \
    if (MODE == 2) { \
      int kr0 = tid >> 5, c40 = (tid & 31)*4; \
      *(float4*)(As[s] + kr0*TFA + c40) = w0; \
      int i1 = tid + 256; int kr1 = i1 >> 5, c41 = (i1 & 31)*4; \
      *(float4*)(As[s] + kr1*TFA + c41) = w1; \
    } else { \
      int r0 = tid >> 2, c40 = (tid & 3)*4; \
      As[s][(c40+0)*TFA + r0] = w0.x; As[s][(c40+1)*TFA + r0] = w0.y; \
      As[s][(c40+2)*TFA + r0] = w0.z; As[s][(c40+3)*TFA + r0] = w0.w; \
      int i1 = tid + 256; int r1 = i1 >> 2, c41 = (i1 & 3)*4; \
      As[s][(c41+0)*TFA + r1] = w1.x; As[s][(c41+1)*TFA + r1] = w1.y; \
      As[s][(c41+2)*TFA + r1] = w1.z; As[s][(c41+3)*TFA + r1] = w1.w; \
    } \
    if (MODE == 0) { \
      int r = tid >> 2, c4 = (tid & 3)*4; \
      Bs[s][(c4+0)*TFB + r] = wb.x; Bs[s][(c4+1)*TFB + r] = wb.y; \
      Bs[s][(c4+2)*TFB + r] = wb.z; Bs[s][(c4+3)*TFB + r] = wb.w; \
    } else { \
      int kr = tid >> 4, c4 = (tid & 15)*4; \
      *(float4*)(Bs[s] + kr*TFB + c4) = wb; \
    } \
  } while (0)

  TG_LOAD(0);
  TG_STORE(0);
  __syncthreads();

  for (int t = 0; t < NT; ++t) {
    int cb = t & 1;
    if (t+1 < NT) TG_LOAD((t+1)*16);
    // ---- compute tile t from stage cb ----
#pragma unroll
    for (int ks = 0; ks < 2; ++ks) {
      int kb = ks*8;
      unsigned ah[2][4], al[2][4];
#pragma unroll
      for (int mt = 0; mt < 2; ++mt) {
        const float* ap = As[cb] + (kb + la3)*TFA + wm + mt*16 + g;
        float f0 = ap[0], f1 = ap[8], f2 = ap[4*TFA], f3 = ap[4*TFA + 8];
        if (SPLIT) {
          float h0 = f2tf(f0), h1 = f2tf(f1), h2 = f2tf(f2), h3 = f2tf(f3);
          ah[mt][0] = __float_as_uint(h0); al[mt][0] = __float_as_uint(f2tf(f0 - h0));
          ah[mt][1] = __float_as_uint(h1); al[mt][1] = __float_as_uint(f2tf(f1 - h1));
          ah[mt][2] = __float_as_uint(h2); al[mt][2] = __float_as_uint(f2tf(f2 - h2));
          ah[mt][3] = __float_as_uint(h3); al[mt][3] = __float_as_uint(f2tf(f3 - h3));
        } else {
          ah[mt][0] = __float_as_uint(f0); ah[mt][1] = __float_as_uint(f1);
          ah[mt][2] = __float_as_uint(f2); ah[mt][3] = __float_as_uint(f3);
        }
      }
#pragma unroll
      for (int nt = 0; nt < 4; ++nt) {
        const float* bp = Bs[cb] + (kb + la3)*TFB + wn + nt*8 + g;
        float bf0 = bp[0], bf1 = bp[4*TFB];
        unsigned bh0, bh1, bl0, bl1;
        if (SPLIT) {
          float h0 = f2tf(bf0), h1 = f2tf(bf1);
          bh0 = __float_as_uint(h0); bl0 = __float_as_uint(f2tf(bf0 - h0));
          bh1 = __float_as_uint(h1); bl1 = __float_as_uint(f2tf(bf1 - h1));
        } else {
          bh0 = __float_as_uint(bf0); bh1 = __float_as_uint(bf1);
          bl0 = bl1 = 0;
        }
#pragma unroll
        for (int mt = 0; mt < 2; ++mt) {
          mma_tf32(acc[mt][nt], ah[mt], bh0, bh1);
          if (SPLIT) {
            mma_tf32(acc[mt][nt], ah[mt], bl0, bl1);
            mma_tf32(acc[mt][nt], al[mt], bh0, bh1);
          }
        }
      }
    }
    if (t+1 < NT) TG_STORE(cb ^ 1);
    __syncthreads();
  }

  int len = (act == 3) ? seq[blockIdx.z] : 0;
#pragma unroll
  for (int mt = 0; mt < 2; ++mt) {
    int mrow = m0 + wm + mt*16 + g;
#pragma unroll
    for (int nt = 0; nt < 4; ++nt) {
      int ncol = n0 + wn + nt*8 + la3*2;
      float b0v = 0.f, b1v = 0.f;
      if (bias && act != 4) { b0v = bias[ncol]; b1v = bias[ncol+1]; }
      float v[4] = { acc[mt][nt][0] + b0v, acc[mt][nt][1] + b1v,
                     acc[mt][nt][2] + b0v, acc[mt][nt][3] + b1v };
      if (act == 1) {
        v[0]=tanhf(v[0]); v[1]=tanhf(v[1]); v[2]=tanhf(v[2]); v[3]=tanhf(v[3]);
      } else if (act == 2) {
#pragma unroll
        for (int q = 0; q < 4; ++q) v[q] = v[q]>=0.f ? v[q] : 0.01f*v[q];
      } else if (act == 3) {
#pragma unroll
        for (int q = 0; q < 4; ++q) {
          int gi = mrow + (q >= 2 ? 8 : 0);
          int gj = ncol + (q & 1);
          v[q] = (gi != gj && gi < len && gj < len) ? expf(v[q]) : 0.0f;
        }
      } else if (act == 4) {
        float pr0 = aux[(size_t)blockIdx.z*TT1*TT + mrow];
        float pr8 = aux[(size_t)blockIdx.z*TT1*TT + mrow + 8];
        v[0] += pr0*bias[ncol]; v[1] += pr0*bias[ncol+1];
        v[2] += pr8*bias[ncol]; v[3] += pr8*bias[ncol+1];
      }
      *(float2*)(Cb + (size_t)mrow*ldc + ncol) = make_float2(v[0], v[1]);
      *(float2*)(Cb + (size_t)(mrow+8)*ldc + ncol) = make_float2(v[2], v[3]);
    }
  }
#undef TG_LOAD
#undef TG_STORE
}

// ---------------- launch ----------------
extern "C" void kernel_launch(void* const* d_in, const int* in_sizes, int n_in,
                              void* d_out, int out_size) {
  (void)in_sizes; (void)n_in; (void)out_size;
  const float* x     = (const float*)d_in[0];
  const int*   seq   = (const int*)  d_in[1];
  const float* W_tp  = (const float*)d_in[2];
  const float* b_tp  = (const float*)d_in[3];
  const float* W_tc  = (const float*)d_in[4];
  const float* b_tc  = (const float*)d_in[5];
  const float* W_fij = (const float*)d_in[6];
  const float* w_root= (const float*)d_in[7];
  const float* r_emb = (const float*)d_in[8];
  const float* W_r   = (const float*)d_in[9];
  const float* b_r   = (const float*)d_in[10];
  const float* W_pc  = (const float*)d_in[11];
  const float* b_pc  = (const float*)d_in[12];
  float* out1 = (float*)d_out;
  float* out2 = out1 + (size_t)BT*SD;

  float *st,*se,*tp,*tc,*gg,*A,*L,*Li,*cat,*cat2;
  cudaGetSymbolAddress((void**)&st,   g_st);
  cudaGetSymbolAddress((void**)&se,   g_se);
  cudaGetSymbolAddress((void**)&tp,   g_tp);
  cudaGetSymbolAddress((void**)&tc,   g_tc);
  cudaGetSymbolAddress((void**)&gg,   g_gg);
  cudaGetSymbolAddress((void**)&A,    g_A);
  cudaGetSymbolAddress((void**)&L,    g_L);
  cudaGetSymbolAddress((void**)&Li,   g_Li);
  cudaGetSymbolAddress((void**)&cat,  g_cat);
  cudaGetSymbolAddress((void**)&cat2, g_cat2);

  const int PANEL_SMEM  = TT*33*4;              // 67584
  const int UPDATE_SMEM = TT*33*4 + NB*132*4;   // 84480
  cudaFuncSetAttribute(panel_k,  cudaFuncAttributeMaxDynamicSharedMemorySize, PANEL_SMEM);
  cudaFuncSetAttribute(update_k, cudaFuncAttributeMaxDynamicSharedMemorySize, UPDATE_SMEM);

  const long long sTT = (long long)TT*TT, sTS = (long long)TT*SD,
                  sTH = (long long)TT*HD, sP = (long long)TT1*TT;
  const float* pij = out2 + TT;

  split_k<<<BT*HD/256, 256>>>(x);
  tgemm_k<0,true><<<dim3(4,128,1),256>>>(st, SD, 0, W_tp, SD, 0, tp, SD, 0, SD, b_tp, 1, 0, 0);
  tgemm_k<0,true><<<dim3(4,128,1),256>>>(st, SD, 0, W_tc, SD, 0, tc, SD, 0, SD, b_tc, 1, 0, 0);
  tgemm_k<1,true><<<dim3(4,128,1),256>>>(tp, SD, 0, W_fij, SD, 0, gg, SD, 0, SD, 0, 0, 0, 0);
  tgemm_k<0,true><<<dim3(8,4,BB),256>>>(gg, SD, sTS, tc, SD, sTS, A, TT, sTT, SD, 0, 3, seq, 0);
  root_k<<<BT*32/256, 256>>>(w_root, seq);
  zcs_k<<<BT/1024, 1024>>>();
  colsum_k<<<dim3(8,BB), 512>>>();
  buildL_k<<<MT/256, 256>>>(seq);
  for (int kb = 0; kb < TT/NB; ++kb) {
    const float* s_ = (kb & 1) ? Li : L;
    float*       d_ = (kb & 1) ? L  : Li;
    panel_k<<<BB, 1024, PANEL_SMEM>>>(s_, d_, kb*NB);
    update_k<<<dim3(4, BB), 1024, UPDATE_SMEM>>>(s_, d_, kb*NB);
  }
  gather_k<<<dim3(4, BB), 1024>>>();
  diag_k<<<BB, TT>>>(out2);
  pij_k<<<dim3(16,16,BB), dim3(32,32)>>>(out2);
  tgemm_k<2,false><<<dim3(4,4,BB),256>>>(pij, TT, sP, se, SD, sTS, cat, HD, sTH, TT, r_emb, 4, 0, out2);
  tgemm_k<1,false><<<dim3(4,4,BB),256>>>(pij, TT, sP, se, SD, sTS, cat + SD, HD, sTH, TT, 0, 0, 0, 0);
  tgemm_k<0,false><<<dim3(4,128,1),256>>>(cat, HD, 0, W_r, HD, 0, cat2, HD, 0, HD, b_r, 2, 0, 0);
  tgemm_k<1,false><<<dim3(4,4,BB),256>>>(pij, TT, sP, cat2, HD, sTH, cat2 + SD, HD, sTH, TT, 0, 0, 0, 0);
  tgemm_k<0,false><<<dim3(4,128,1),256>>>(cat2, HD, 0, W_pc, HD, 0, out1, SD, 0, HD, b_pc, 2, 0, 0);
}

// round 15
// speedup vs baseline: 1.2430x; 1.0332x over previous
#include <cuda_runtime.h>
#include <math.h>

#define BB 32
#define TT 512
#define TT1 513
#define SD 256
#define HD 512
#define BT (BB*TT)
#define MS (BT*SD)
#define MT (BT*TT)
#define NB 32

__device__ __align__(128) float g_st[MS], g_se[MS], g_tp[MS], g_tc[MS], g_gg[MS];
__device__ __align__(128) float g_A[MT], g_L[MT], g_Li[MT], g_cat[MT], g_cat2[MT];
__device__ __align__(128) float g_P[BB*TT*NB];
__device__ __align__(128) float g_cs[BT], g_ar[BT], g_dg[BT];
__device__ __align__(128) int   g_piv[BT];
__device__ __align__(128) int   g_srcrow[BT];
__device__ __align__(128) int   g_flag[BB];

// ---------------- elementwise ----------------
__global__ void split_k(const float* __restrict__ x) {
  int idx = blockIdx.x*blockDim.x + threadIdx.x;
  int c = idx & 511; int bt = idx >> 9;
  const float* xp = x + (size_t)bt*HD;
  if (c < SD) g_se[(size_t)bt*SD + c] = xp[c + ((c >= 128) ? 128 : 0)];
  else { int cc = c - SD; g_st[(size_t)bt*SD + cc] = xp[cc + 128 + ((cc >= 128) ? 128 : 0)]; }
}

// root scores; lane1 zeroes g_cs for the later colsum atomics
__global__ void root_k(const float* __restrict__ wr, const int* __restrict__ seq) {
  int g = blockIdx.x*blockDim.x + threadIdx.x;
  int w = g >> 5, lane = g & 31;
  if (w >= BT) return;
  if (lane == 1) g_cs[w] = 0.0f;
  const float* s = g_st + (size_t)w*SD;
  float acc = 0.f;
  for (int c = lane; c < SD; c += 32) acc += s[c]*wr[c];
  for (int o = 16; o > 0; o >>= 1) acc += __shfl_down_sync(0xffffffffu, acc, o);
  if (lane == 0) {
    int b = w >> 9, t = w & 511;
    g_ar[w] = (t < seq[b]) ? expf(acc) : 0.0f;
  }
}

__global__ void colsum_k() {
  int b = blockIdx.y, j = threadIdx.x;
  int i0 = blockIdx.x*64;
  const float* a = g_A + (size_t)b*TT*TT;
  float s = 0.f;
  #pragma unroll 8
  for (int i = i0; i < i0+64; ++i) s += a[(size_t)i*TT + j];
  atomicAdd(&g_cs[b*TT + j], s);
}

__global__ void buildL_k(const int* __restrict__ seq) {
  int idx = blockIdx.x*blockDim.x + threadIdx.x;
  if (idx < BB) g_flag[idx] = 0;
  int j = idx & 511, i = (idx >> 9) & 511, b = idx >> 18;
  float v;
  if (i == 0) v = g_ar[b*TT + j];
  else {
    v = -g_A[idx];
    if (i == j) v += g_cs[b*TT + j] + ((j >= seq[b]) ? 1.0f : 0.0f);
  }
  g_L[idx] = v;
}

// ---------------- fused blocked-GJ round (panel + update in one launch) ----------------
// grid (4, BB): CTA x==0 runs the register-resident panel for matrix b, publishes
// P/sigma/pivots, sets g_flag[b]=r+1, then does update slice 0 reusing its smem stage.
// CTAs x=1..3 spin on the flag, then do slices 1..3. 128 CTAs <= 148 SMs: co-resident.
__global__ __launch_bounds__(1024) void round_k(const float* __restrict__ srcM,
                                                float* __restrict__ dstM, int k0, int r) {
  extern __shared__ float sm[];      // [0,TT*33) Ps/stage ; [TT*33, +NB*132) Rs
  float* PsS = sm;
  float* Rs  = sm + TT*33;
  __shared__ float colA[TT], colB[TT];
  __shared__ float rowk[NB];
  __shared__ int cur[TT], logpos[TT];
  __shared__ float sPinv; __shared__ int sPr;
  __shared__ int smap[TT];
  int b = blockIdx.y, x = blockIdx.x, tid = threadIdx.x;
  const float* src = srcM + (size_t)b*TT*TT;
  float* dst = dstM + (size_t)b*TT*TT;
  float* Pg = g_P + (size_t)b*TT*NB;

  if (x == 0) {
    // ================= panel =================
    int c = tid >> 5, lane = tid & 31;
    for (int idx = tid; idx < TT*NB; idx += 1024) {
      int i = idx >> 5, cc = idx & 31;
      PsS[i*33+cc] = src[(size_t)i*TT + k0 + cc];
    }
    if (tid < TT) { cur[tid] = tid; logpos[tid] = tid; }
    __syncthreads();
    float val[16];
#pragma unroll
    for (int w = 0; w < 16; ++w) val[w] = PsS[(lane+32*w)*33 + c];
    if (c == 0) {
      float bv = -1.f; int bp = lane; float bs = 0.f;
#pragma unroll
      for (int w = 0; w < 16; ++w) {
        int p = lane + 32*w;
        colA[p] = val[w];
        if (p >= k0) {
          float av = fabsf(val[w]);
          if (av > bv) { bv = av; bp = p; bs = val[w]; }
        }
      }
      for (int o = 16; o > 0; o >>= 1) {
        float v2 = __shfl_down_sync(0xffffffffu, bv, o);
        int   p2 = __shfl_down_sync(0xffffffffu, bp, o);
        float s2 = __shfl_down_sync(0xffffffffu, bs, o);
        if (v2 > bv) { bv = v2; bp = p2; bs = s2; }
      }
      if (lane == 0) {
        int lp = logpos[bp];
        int pk = cur[k0];
        cur[k0] = bp; cur[lp] = pk;
        logpos[bp] = k0; logpos[pk] = lp;
        g_piv[b*TT + k0] = lp;
        sPr = bp; sPinv = 1.0f / bs;
      }
    }
    for (int kk = 0; kk < NB; ++kk) {
      __syncthreads();
      int pr = sPr; float pinv = sPinv;
#pragma unroll
      for (int w = 0; w < 16; ++w) {
        if (lane + 32*w == pr) {
          float v = (c == kk) ? 1.0f : val[w];
          v *= pinv;
          val[w] = v;
          rowk[c] = v;
        }
      }
      __syncthreads();
      float rk = rowk[c];
      const float* colR = (kk & 1) ? colB : colA;
#pragma unroll
      for (int w = 0; w < 16; ++w) {
        int p = lane + 32*w;
        if (p != pr) {
          float m = colR[p];
          float cv = (c == kk) ? 0.0f : val[w];
          val[w] = cv - m*rk;
        }
      }
      if (kk < NB-1 && c == kk+1) {
        float* colW = (kk & 1) ? colA : colB;
        int kn = k0 + kk + 1;
        float bv = -1.f; int bp = lane; float bs = 0.f;
#pragma unroll
        for (int w = 0; w < 16; ++w) {
          int p = lane + 32*w;
          colW[p] = val[w];
          if (logpos[p] >= kn) {
            float av = fabsf(val[w]);
            if (av > bv) { bv = av; bp = p; bs = val[w]; }
          }
        }
        for (int o = 16; o > 0; o >>= 1) {
          float v2 = __shfl_down_sync(0xffffffffu, bv, o);
          int   p2 = __shfl_down_sync(0xffffffffu, bp, o);
          float s2 = __shfl_down_sync(0xffffffffu, bs, o);
          if (v2 > bv) { bv = v2; bp = p2; bs = s2; }
        }
        __syncwarp();
        if (lane == 0) {
          int lp = logpos[bp];
          int pk = cur[kn];
          cur[kn] = bp; cur[lp] = pk;
          logpos[bp] = kn; logpos[pk] = lp;
          g_piv[b*TT + kn] = lp;
          sPr = bp; sPinv = 1.0f / bs;
        }
      }
    }
    // epilogue: scatter registers to logical order; publish P, sigma, flag
#pragma unroll
    for (int w = 0; w < 16; ++w) {
      int p = lane + 32*w;
      PsS[logpos[p]*33 + c] = val[w];
    }
    if (tid < TT) { g_srcrow[b*TT + tid] = cur[tid]; smap[tid] = cur[tid]; }
    __syncthreads();
    for (int idx = tid; idx < TT*NB; idx += 1024) {
      int i = idx >> 5, cc = idx & 31;
      Pg[i*32+cc] = PsS[i*33+cc];
    }
    __syncthreads();
    if (tid == 0) { __threadfence(); atomicExch(&g_flag[b], r+1); }
    // PsS already holds P in logical order -> reuse for slice 0
  } else {
    if (tid == 0) {
      while (atomicAdd(&g_flag[b], 0) < r+1) {}
      __threadfence();
    }
    __syncthreads();
    if (tid < TT) smap[tid] = g_srcrow[b*TT + tid];
    __syncthreads();
    for (int idx = tid; idx < TT*NB; idx += 1024) {
      int i = idx >> 5, cc = idx & 31;
      PsS[i*33+cc] = Pg[i*32+cc];
    }
  }
  // ================= update slice x =================
  int jbase = x*128;
  for (int idx = tid; idx < NB*128; idx += 1024) {
    int k = idx >> 7, cc = idx & 127;
    Rs[k*132+cc] = src[(size_t)smap[k0+k]*TT + jbase + cc];
  }
  __syncthreads();
  int tx = tid & 31, ty = tid >> 5;
  int j = jbase + tx*4;
  if (j >= k0 && j < k0 + NB) {
    int pc = j - k0;
    for (int rr = 0; rr < 4; ++rr) {
      int i0 = rr*128 + ty*4;
#pragma unroll
      for (int q = 0; q < 4; ++q) {
        int i = i0 + q;
        *(float4*)(dst + (size_t)i*TT + j) = *(const float4*)(Pg + (size_t)i*32 + pc);
      }
    }
    return;
  }
  for (int rr = 0; rr < 4; ++rr) {
    int i0 = rr*128 + ty*4;
    float acc[4][4] = {};
#pragma unroll 8
    for (int k = 0; k < NB; ++k) {
      float4 rv = *(const float4*)(Rs + k*132 + tx*4);
      float p0 = PsS[(i0+0)*33+k], p1 = PsS[(i0+1)*33+k];
      float p2 = PsS[(i0+2)*33+k], p3 = PsS[(i0+3)*33+k];
      acc[0][0]+=p0*rv.x; acc[0][1]+=p0*rv.y; acc[0][2]+=p0*rv.z; acc[0][3]+=p0*rv.w;
      acc[1][0]+=p1*rv.x; acc[1][1]+=p1*rv.y; acc[1][2]+=p1*rv.z; acc[1][3]+=p1*rv.w;
      acc[2][0]+=p2*rv.x; acc[2][1]+=p2*rv.y; acc[2][2]+=p2*rv.z; acc[2][3]+=p2*rv.w;
      acc[3][0]+=p3*rv.x; acc[3][1]+=p3*rv.y; acc[3][2]+=p3*rv.z; acc[3][3]+=p3*rv.w;
    }
#pragma unroll
    for (int q = 0; q < 4; ++q) {
      int i = i0 + q;
      float4 res;
      if (i >= k0 && i < k0 + NB) res = make_float4(0.f,0.f,0.f,0.f);
      else res = *(const float4*)(src + (size_t)smap[i]*TT + j);
      res.x += acc[q][0]; res.y += acc[q][1]; res.z += acc[q][2]; res.w += acc[q][3];
      *(float4*)(dst + (size_t)i*TT + j) = res;
    }
  }
}

// gather with fused diag/p_root extraction
__global__ __launch_bounds__(1024) void gather_k(float* __restrict__ out2) {
  __shared__ int arr[TT];
  int b = blockIdx.y, tid = threadIdx.x;
  if (tid == 0) {
    for (int j = 0; j < TT; ++j) arr[j] = j;
    for (int l = TT-1; l >= 0; --l) {
      int p = g_piv[b*TT + l];
      if (p != l) { int t = arr[l]; arr[l] = arr[p]; arr[p] = t; }
    }
  }
  __syncthreads();
  const float* a = g_L + (size_t)b*TT*TT;
  float* o = g_Li + (size_t)b*TT*TT;
  int base = blockIdx.x * 128 * TT;
  for (int idx = tid; idx < 128*TT; idx += 1024) {
    int i = idx >> 9, j = idx & 511;
    int gi = blockIdx.x*128 + i;
    float v = a[(size_t)gi*TT + arr[j]];
    o[base + idx] = v;
    if (j == 0) out2[(size_t)b*TT1*TT + gi] = g_ar[b*TT + gi] * v;
    if (gi == j) g_dg[b*TT + j] = v;
  }
}

__global__ __launch_bounds__(1024) void pij_k(float* __restrict__ out2) {
  __shared__ float Ts[32][33];
  int b = blockIdx.z;
  int i0 = blockIdx.y*32, j0 = blockIdx.x*32;
  int tx = threadIdx.x, ty = threadIdx.y;
  const float* L = g_Li + (size_t)b*TT*TT;
  Ts[ty][tx] = L[(size_t)(j0+ty)*TT + i0 + tx];
  __syncthreads();
  int i = i0 + ty, j = j0 + tx;
  float av  = g_A[(size_t)b*TT*TT + (size_t)i*TT + j];
  float dj  = (j > 0) ? g_dg[b*TT + j] : 0.0f;
  float lji = (i > 0) ? Ts[tx][ty] : 0.0f;
  out2[(size_t)b*TT1*TT + (size_t)(i+1)*TT + j] = av * (dj - lji);
}

// ---------------- tf32 tensor-core GEMM (double-buffered pipeline) ----------------
// act: 0 none, 1 tanh, 2 leaky, 3 exp+mask, 4 add p_root*root_emb (aux=out2 slab, bias=root_emb)
#define TFA 136
#define TFB 72
__device__ __forceinline__ float f2tf(float f) {
  unsigned u; asm("cvt.rna.tf32.f32 %0, %1;" : "=r"(u) : "f"(f));
  return __uint_as_float(u);
}
__device__ __forceinline__ void mma_tf32(float* d, const unsigned* a, unsigned b0, unsigned b1) {
  asm volatile("mma.sync.aligned.m16n8k8.row.col.f32.tf32.tf32.f32 "
    "{%0,%1,%2,%3}, {%4,%5,%6,%7}, {%8,%9}, {%0,%1,%2,%3};"
    : "+f"(d[0]), "+f"(d[1]), "+f"(d[2]), "+f"(d[3])
    : "r"(a[0]), "r"(a[1]), "r"(a[2]), "r"(a[3]), "r"(b0), "r"(b1));
}
template<int MODE, bool SPLIT>
__global__ __launch_bounds__(256)
void tgemm_k(const float* __restrict__ A, int lda, long long sA,
             const float* __restrict__ B, int ldb, long long sB,
             float* __restrict__ C, int ldc, long long sC,
             int K, const float* __restrict__ bias, int act, const int* __restrict__ seq,
             const float* __restrict__ aux)
{
  __shared__ __align__(16) float As[2][16*TFA];
  __shared__ __align__(16) float Bs[2][16*TFB];
  int tid = threadIdx.x;
  int m0 = blockIdx.y*128, n0 = blockIdx.x*64;
  const float* Ab = A + (size_t)blockIdx.z*sA;
  const float* Bb = B + (size_t)blockIdx.z*sB;
  float* Cb = C + (size_t)blockIdx.z*sC;
  int warp = tid>>5, lane = tid&31;
  int wm = (warp&3)*32, wn = (warp>>2)*32;
  int g = lane>>2, la3 = lane&3;
  float acc[2][4][4];
#pragma unroll
  for(int a=0;a<2;a++)
#pragma unroll
    for(int b=0;b<4;b++)
#pragma unroll
      for(int c=0;c<4;c++) acc[a][b][c]=0.f;

  const int NT = K >> 4;
  float4 va0, va1, vb;

#define TG_LOAD(k0) do { \
    if (MODE == 2) { \
      int kr0 = tid >> 5, c40 = (tid & 31)*4; \
      va0 = *(const float4*)(Ab + (size_t)((k0)+kr0)*lda + m0 + c40); \
      int i1 = tid + 256; int kr1 = i1 >> 5, c41 = (i1 & 31)*4; \
      va1 = *(const float4*)(Ab + (size_t)((k0)+kr1)*lda + m0 + c41); \
    } else { \
      int r0 = tid >> 2, c40 = (tid & 3)*4; \
      va0 = *(const float4*)(Ab + (size_t)(m0+r0)*lda + (k0) + c40); \
      int i1 = tid + 256; int r1 = i1 >> 2, c41 = (i1 & 3)*4; \
      va1 = *(const float4*)(Ab + (size_t)(m0+r1)*lda + (k0) + c41); \
    } \
    if (MODE == 0) { \
      int r = tid >> 2, c4 = (tid & 3)*4; \
      vb = *(const float4*)(Bb + (size_t)(n0+r)*ldb + (k0) + c4); \
    } else { \
      int kr = tid >> 4, c4 = (tid & 15)*4; \
      vb = *(const float4*)(Bb + (size_t)((k0)+kr)*ldb + n0 + c4); \
    } \
  } while (0)

#define TG_STORE(s) do { \
    float4 w0 = va0, w1 = va1, wb = vb; \
    if (!SPLIT) { \
      w0.x = f2tf(w0.x); w0.y = f2tf(w0.y); w0.z = f2tf(w0.z); w0.w = f2tf(w0.w); \
      w1.x = f2tf(w1.x); w1.y = f2tf(w1.y); w1.z = f2tf(w1.z); w1.w = f2tf(w1.w); \
      wb.x = f2tf(wb.x); wb.y = f2tf(wb.y); wb.z = f2tf(wb.z); wb.w = f2tf(wb.w); \
    } \
    if (MODE == 2) { \
      int kr0 = tid >> 5, c40 = (tid & 31)*4; \
      *(float4*)(As[s] + kr0*TFA + c40) = w0; \
      int i1 = tid + 256; int kr1 = i1 >> 5, c41 = (i1 & 31)*4; \
      *(float4*)(As[s] + kr1*TFA + c41) = w1; \
    } else { \
      int r0 = tid >> 2, c40 = (tid & 3)*4; \
      As[s][(c40+0)*TFA + r0] = w0.x; As[s][(c40+1)*TFA + r0] = w0.y; \
      As[s][(c40+2)*TFA + r0] = w0.z; As[s][(c40+3)*TFA + r0] = w0.w; \
      int i1 = tid + 256; int r1 = i1 >> 2, c41 = (i1 & 3)*4; \
      As[s][(c41+0)*TFA + r1] = w1.x; As[s][(c41+1)*TFA + r1] = w1.y; \
      As[s][(c41+2)*TFA + r1] = w1.z; As[s][(c41+3)*TFA + r1] = w1.w; \
    } \
    if (MODE == 0) { \
      int r = tid >> 2, c4 = (tid & 3)*4; \
      Bs[s][(c4+0)*TFB + r] = wb.x; Bs[s][(c4+1)*TFB + r] = wb.y; \
      Bs[s][(c4+2)*TFB + r] = wb.z; Bs[s][(c4+3)*TFB + r] = wb.w; \
    } else { \
      int kr = tid >> 4, c4 = (tid & 15)*4; \
      *(float4*)(Bs[s] + kr*TFB + c4) = wb; \
    } \
  } while (0)

  TG_LOAD(0);
  TG_STORE(0);
  __syncthreads();

  for (int t = 0; t < NT; ++t) {
    int cb = t & 1;
    if (t+1 < NT) TG_LOAD((t+1)*16);
#pragma unroll
    for (int ks = 0; ks < 2; ++ks) {
      int kb = ks*8;
      unsigned ah[2][4], al[2][4];
#pragma unroll
      for (int mt = 0; mt < 2; ++mt) {
        const float* ap = As[cb] + (kb + la3)*TFA + wm + mt*16 + g;
        float f0 = ap[0], f1 = ap[8], f2 = ap[4*TFA], f3 = ap[4*TFA + 8];
        if (SPLIT) {
          float h0 = f2tf(f0), h1 = f2tf(f1), h2 = f2tf(f2), h3 = f2tf(f3);
          ah[mt][0] = __float_as_uint(h0); al[mt][0] = __float_as_uint(f2tf(f0 - h0));
          ah[mt][1] = __float_as_uint(h1); al[mt][1] = __float_as_uint(f2tf(f1 - h1));
          ah[mt][2] = __float_as_uint(h2); al[mt][2] = __float_as_uint(f2tf(f2 - h2));
          ah[mt][3] = __float_as_uint(h3); al[mt][3] = __float_as_uint(f2tf(f3 - h3));
        } else {
          ah[mt][0] = __float_as_uint(f0); ah[mt][1] = __float_as_uint(f1);
          ah[mt][2] = __float_as_uint(f2); ah[mt][3] = __float_as_uint(f3);
        }
      }
#pragma unroll
      for (int nt = 0; nt < 4; ++nt) {
        const float* bp = Bs[cb] + (kb + la3)*TFB + wn + nt*8 + g;
        float bf0 = bp[0], bf1 = bp[4*TFB];
        unsigned bh0, bh1, bl0, bl1;
        if (SPLIT) {
          float h0 = f2tf(bf0), h1 = f2tf(bf1);
          bh0 = __float_as_uint(h0); bl0 = __float_as_uint(f2tf(bf0 - h0));
          bh1 = __float_as_uint(h1); bl1 = __float_as_uint(f2tf(bf1 - h1));
        } else {
          bh0 = __float_as_uint(bf0); bh1 = __float_as_uint(bf1);
          bl0 = bl1 = 0;
        }
#pragma unroll
        for (int mt = 0; mt < 2; ++mt) {
          mma_tf32(acc[mt][nt], ah[mt], bh0, bh1);
          if (SPLIT) {
            mma_tf32(acc[mt][nt], ah[mt], bl0, bl1);
            mma_tf32(acc[mt][nt], al[mt], bh0, bh1);
          }
        }
      }
    }
    if (t+1 < NT) TG_STORE(cb ^ 1);
    __syncthreads();
  }

  int len = (act == 3) ? seq[blockIdx.z] : 0;
#pragma unroll
  for (int mt = 0; mt < 2; ++mt) {
    int mrow = m0 + wm + mt*16 + g;
#pragma unroll
    for (int nt = 0; nt < 4; ++nt) {
      int ncol = n0 + wn + nt*8 + la3*2;
      float b0v = 0.f, b1v = 0.f;
      if (bias && act != 4) { b0v = bias[ncol]; b1v = bias[ncol+1]; }
      float v[4] = { acc[mt][nt][0] + b0v, acc[mt][nt][1] + b1v,
                     acc[mt][nt][2] + b0v, acc[mt][nt][3] + b1v };
      if (act == 1) {
        v[0]=tanhf(v[0]); v[1]=tanhf(v[1]); v[2]=tanhf(v[2]); v[3]=tanhf(v[3]);
      } else if (act == 2) {
#pragma unroll
        for (int q = 0; q < 4; ++q) v[q] = v[q]>=0.f ? v[q] : 0.01f*v[q];
      } else if (act == 3) {
#pragma unroll
        for (int q = 0; q < 4; ++q) {
          int gi = mrow + (q >= 2 ? 8 : 0);
          int gj = ncol + (q & 1);
          v[q] = (gi != gj && gi < len && gj < len) ? expf(v[q]) : 0.0f;
        }
      } else if (act == 4) {
        float pr0 = aux[(size_t)blockIdx.z*TT1*TT + mrow];
        float pr8 = aux[(size_t)blockIdx.z*TT1*TT + mrow + 8];
        v[0] += pr0*bias[ncol]; v[1] += pr0*bias[ncol+1];
        v[2] += pr8*bias[ncol]; v[3] += pr8*bias[ncol+1];
      }
      *(float2*)(Cb + (size_t)mrow*ldc + ncol) = make_float2(v[0], v[1]);
      *(float2*)(Cb + (size_t)(mrow+8)*ldc + ncol) = make_float2(v[2], v[3]);
    }
  }
#undef TG_LOAD
#undef TG_STORE
}

// ---------------- launch ----------------
extern "C" void kernel_launch(void* const* d_in, const int* in_sizes, int n_in,
                              void* d_out, int out_size) {
  (void)in_sizes; (void)n_in; (void)out_size;
  const float* x     = (const float*)d_in[0];
  const int*   seq   = (const int*)  d_in[1];
  const float* W_tp  = (const float*)d_in[2];
  const float* b_tp  = (const float*)d_in[3];
  const float* W_tc  = (const float*)d_in[4];
  const float* b_tc  = (const float*)d_in[5];
  const float* W_fij = (const float*)d_in[6];
  const float* w_root= (const float*)d_in[7];
  const float* r_emb = (const float*)d_in[8];
  const float* W_r   = (const float*)d_in[9];
  const float* b_r   = (const float*)d_in[10];
  const float* W_pc  = (const float*)d_in[11];
  const float* b_pc  = (const float*)d_in[12];
  float* out1 = (float*)d_out;
  float* out2 = out1 + (size_t)BT*SD;

  float *st,*se,*tp,*tc,*gg,*A,*L,*Li,*cat,*cat2;
  cudaGetSymbolAddress((void**)&st,   g_st);
  cudaGetSymbolAddress((void**)&se,   g_se);
  cudaGetSymbolAddress((void**)&tp,   g_tp);
  cudaGetSymbolAddress((void**)&tc,   g_tc);
  cudaGetSymbolAddress((void**)&gg,   g_gg);
  cudaGetSymbolAddress((void**)&A,    g_A);
  cudaGetSymbolAddress((void**)&L,    g_L);
  cudaGetSymbolAddress((void**)&Li,   g_Li);
  cudaGetSymbolAddress((void**)&cat,  g_cat);
  cudaGetSymbolAddress((void**)&cat2, g_cat2);

  const int ROUND_SMEM = TT*33*4 + NB*132*4;   // 84480
  cudaFuncSetAttribute(round_k, cudaFuncAttributeMaxDynamicSharedMemorySize, ROUND_SMEM);

  const long long sTT = (long long)TT*TT, sTS = (long long)TT*SD,
                  sTH = (long long)TT*HD, sP = (long long)TT1*TT;
  const float* pij = out2 + TT;

  split_k<<<BT*HD/256, 256>>>(x);
  tgemm_k<0,true><<<dim3(4,128,1),256>>>(st, SD, 0, W_tp, SD, 0, tp, SD, 0, SD, b_tp, 1, 0, 0);
  tgemm_k<0,true><<<dim3(4,128,1),256>>>(st, SD, 0, W_tc, SD, 0, tc, SD, 0, SD, b_tc, 1, 0, 0);
  tgemm_k<1,true><<<dim3(4,128,1),256>>>(tp, SD, 0, W_fij, SD, 0, gg, SD, 0, SD, 0, 0, 0, 0);
  tgemm_k<0,true><<<dim3(8,4,BB),256>>>(gg, SD, sTS, tc, SD, sTS, A, TT, sTT, SD, 0, 3, seq, 0);
  root_k<<<BT*32/256, 256>>>(w_root, seq);
  colsum_k<<<dim3(8,BB), 512>>>();
  buildL_k<<<MT/256, 256>>>(seq);
  for (int kb = 0; kb < TT/NB; ++kb) {
    const float* s_ = (kb & 1) ? Li : L;
    float*       d_ = (kb & 1) ? L  : Li;
    round_k<<<dim3(4, BB), 1024, ROUND_SMEM>>>(s_, d_, kb*NB, kb);
  }
  gather_k<<<dim3(4, BB), 1024>>>(out2);
  pij_k<<<dim3(16,16,BB), dim3(32,32)>>>(out2);
  tgemm_k<2,false><<<dim3(4,4,BB),256>>>(pij, TT, sP, se, SD, sTS, cat, HD, sTH, TT, r_emb, 4, 0, out2);
  tgemm_k<1,false><<<dim3(4,4,BB),256>>>(pij, TT, sP, se, SD, sTS, cat + SD, HD, sTH, TT, 0, 0, 0, 0);
  tgemm_k<0,false><<<dim3(4,128,1),256>>>(cat, HD, 0, W_r, HD, 0, cat2, HD, 0, HD, b_r, 2, 0, 0);
  tgemm_k<1,false><<<dim3(4,4,BB),256>>>(pij, TT, sP, cat2, HD, sTH, cat2 + SD, HD, sTH, TT, 0, 0, 0, 0);
  tgemm_k<0,false><<<dim3(4,128,1),256>>>(cat2, HD, 0, W_pc, HD, 0, out1, SD, 0, HD, b_pc, 2, 0, 0);
}

// round 16
// speedup vs baseline: 1.2775x; 1.0277x over previous
#include <cuda_runtime.h>
#include <math.h>

#define BB 32
#define TT 512
#define TT1 513
#define SD 256
#define HD 512
#define BT (BB*TT)
#define MS (BT*SD)
#define MT (BT*TT)
#define NB 32

__device__ __align__(128) float g_st[MS], g_se[MS], g_tp[MS], g_tc[MS], g_gg[MS];
__device__ __align__(128) float g_A[MT], g_L[MT], g_Li[MT], g_cat[MT], g_cat2[MT];
__device__ __align__(128) float g_P[BB*TT*NB];
__device__ __align__(128) float g_cs[BT], g_ar[BT], g_dg[BT];
__device__ __align__(128) int   g_piv[BT];
__device__ __align__(128) int   g_srcrow[BT];
__device__ __align__(128) int   g_arr[BT];
__device__ __align__(128) int   g_flag[BB];
__device__ __align__(128) int   g_done[BB];

// ---------------- elementwise ----------------
__global__ void split_k(const float* __restrict__ x) {
  int idx = blockIdx.x*blockDim.x + threadIdx.x;
  int c = idx & 511; int bt = idx >> 9;
  const float* xp = x + (size_t)bt*HD;
  if (c < SD) g_se[(size_t)bt*SD + c] = xp[c + ((c >= 128) ? 128 : 0)];
  else { int cc = c - SD; g_st[(size_t)bt*SD + cc] = xp[cc + 128 + ((cc >= 128) ? 128 : 0)]; }
}

__global__ void root_k(const float* __restrict__ wr, const int* __restrict__ seq) {
  int g = blockIdx.x*blockDim.x + threadIdx.x;
  int w = g >> 5, lane = g & 31;
  if (w >= BT) return;
  if (lane == 1) g_cs[w] = 0.0f;
  const float* s = g_st + (size_t)w*SD;
  float acc = 0.f;
  for (int c = lane; c < SD; c += 32) acc += s[c]*wr[c];
  for (int o = 16; o > 0; o >>= 1) acc += __shfl_down_sync(0xffffffffu, acc, o);
  if (lane == 0) {
    int b = w >> 9, t = w & 511;
    g_ar[w] = (t < seq[b]) ? expf(acc) : 0.0f;
  }
}

__global__ void colsum_k() {
  int b = blockIdx.y, j = threadIdx.x;
  int i0 = blockIdx.x*64;
  const float* a = g_A + (size_t)b*TT*TT;
  float s = 0.f;
  #pragma unroll 8
  for (int i = i0; i < i0+64; ++i) s += a[(size_t)i*TT + j];
  atomicAdd(&g_cs[b*TT + j], s);
}

__global__ void buildL_k(const int* __restrict__ seq) {
  int idx = blockIdx.x*blockDim.x + threadIdx.x;
  if (idx < BB) { g_flag[idx] = 0; g_done[idx] = 0; }
  int j = idx & 511, i = (idx >> 9) & 511, b = idx >> 18;
  float v;
  if (i == 0) v = g_ar[b*TT + j];
  else {
    v = -g_A[idx];
    if (i == j) v += g_cs[b*TT + j] + ((j >= seq[b]) ? 1.0f : 0.0f);
  }
  g_L[idx] = v;
}

// ---------------- persistent blocked-GJ inverse (all 16 rounds in one launch) ----------------
// grid (4, BB), 128 co-resident CTAs. Per matrix b, per round r:
//   CTA x==0: wait g_done[b]>=4r -> panel -> publish P/sigma -> g_flag[b]=r+1 -> slice0 -> done++
//   CTA x>0 : wait g_flag[b]>=r+1 -> slice x -> done++
// Slice x only reads its own 128-col stripe of SRC (written by the same CTA last round).
__global__ __launch_bounds__(1024) void inv_k(float* __restrict__ Lb, float* __restrict__ Lib) {
  extern __shared__ float sm[];      // [0,TT*33) PsS ; [TT*33,+NB*132) Rs
  float* PsS = sm;
  float* Rs  = sm + TT*33;
  __shared__ float colA[TT], colB[TT];
  __shared__ float rowk[NB];
  __shared__ int cur[TT], logpos[TT];
  __shared__ float sPinv; __shared__ int sPr;
  __shared__ int smap[TT];
  int b = blockIdx.y, x = blockIdx.x, tid = threadIdx.x;
  float* Pg = g_P + (size_t)b*TT*NB;

  for (int r = 0; r < TT/NB; ++r) {
    int k0 = r*NB;
    const float* src = ((r & 1) ? Lib : Lb) + (size_t)b*TT*TT;
    float*       dst = ((r & 1) ? Lb  : Lib) + (size_t)b*TT*TT;
    __syncthreads();   // smem reuse (WAR) between rounds

    if (x == 0) {
      if (tid == 0 && r > 0) {
        while (atomicAdd(&g_done[b], 0) < 4*r) {}
        __threadfence();
      }
      __syncthreads();
      // ================= panel =================
      int c = tid >> 5, lane = tid & 31;
      for (int idx = tid; idx < TT*NB; idx += 1024) {
        int i = idx >> 5, cc = idx & 31;
        PsS[i*33+cc] = src[(size_t)i*TT + k0 + cc];
      }
      if (tid < TT) { cur[tid] = tid; logpos[tid] = tid; }
      __syncthreads();
      float val[16];
#pragma unroll
      for (int w = 0; w < 16; ++w) val[w] = PsS[(lane+32*w)*33 + c];
      if (c == 0) {
        float bv = -1.f; int bp = lane; float bs = 0.f;
#pragma unroll
        for (int w = 0; w < 16; ++w) {
          int p = lane + 32*w;
          colA[p] = val[w];
          if (p >= k0) {
            float av = fabsf(val[w]);
            if (av > bv) { bv = av; bp = p; bs = val[w]; }
          }
        }
        for (int o = 16; o > 0; o >>= 1) {
          float v2 = __shfl_down_sync(0xffffffffu, bv, o);
          int   p2 = __shfl_down_sync(0xffffffffu, bp, o);
          float s2 = __shfl_down_sync(0xffffffffu, bs, o);
          if (v2 > bv) { bv = v2; bp = p2; bs = s2; }
        }
        if (lane == 0) {
          int lp = logpos[bp];
          int pk = cur[k0];
          cur[k0] = bp; cur[lp] = pk;
          logpos[bp] = k0; logpos[pk] = lp;
          g_piv[b*TT + k0] = lp;
          sPr = bp; sPinv = 1.0f / bs;
        }
      }
      for (int kk = 0; kk < NB; ++kk) {
        __syncthreads();
        int pr = sPr; float pinv = sPinv;
#pragma unroll
        for (int w = 0; w < 16; ++w) {
          if (lane + 32*w == pr) {
            float v = (c == kk) ? 1.0f : val[w];
            v *= pinv;
            val[w] = v;
            rowk[c] = v;
          }
        }
        __syncthreads();
        float rk = rowk[c];
        const float* colR = (kk & 1) ? colB : colA;
#pragma unroll
        for (int w = 0; w < 16; ++w) {
          int p = lane + 32*w;
          if (p != pr) {
            float m = colR[p];
            float cv = (c == kk) ? 0.0f : val[w];
            val[w] = cv - m*rk;
          }
        }
        if (kk < NB-1 && c == kk+1) {
          float* colW = (kk & 1) ? colA : colB;
          int kn = k0 + kk + 1;
          float bv = -1.f; int bp = lane; float bs = 0.f;
#pragma unroll
          for (int w = 0; w < 16; ++w) {
            int p = lane + 32*w;
            colW[p] = val[w];
            if (logpos[p] >= kn) {
              float av = fabsf(val[w]);
              if (av > bv) { bv = av; bp = p; bs = val[w]; }
            }
          }
          for (int o = 16; o > 0; o >>= 1) {
            float v2 = __shfl_down_sync(0xffffffffu, bv, o);
            int   p2 = __shfl_down_sync(0xffffffffu, bp, o);
            float s2 = __shfl_down_sync(0xffffffffu, bs, o);
            if (v2 > bv) { bv = v2; bp = p2; bs = s2; }
          }
          __syncwarp();
          if (lane == 0) {
            int lp = logpos[bp];
            int pk = cur[kn];
            cur[kn] = bp; cur[lp] = pk;
            logpos[bp] = kn; logpos[pk] = lp;
            g_piv[b*TT + kn] = lp;
            sPr = bp; sPinv = 1.0f / bs;
          }
        }
      }
#pragma unroll
      for (int w = 0; w < 16; ++w) {
        int p = lane + 32*w;
        PsS[logpos[p]*33 + c] = val[w];
      }
      if (tid < TT) { g_srcrow[b*TT + tid] = cur[tid]; smap[tid] = cur[tid]; }
      __syncthreads();
      for (int idx = tid; idx < TT*NB; idx += 1024) {
        int i = idx >> 5, cc = idx & 31;
        Pg[i*32+cc] = PsS[i*33+cc];
      }
      __syncthreads();
      if (tid == 0) { __threadfence(); atomicExch(&g_flag[b], r+1); }
    } else {
      if (tid == 0) {
        while (atomicAdd(&g_flag[b], 0) < r+1) {}
        __threadfence();
      }
      __syncthreads();
      if (tid < TT) smap[tid] = g_srcrow[b*TT + tid];
      __syncthreads();
      for (int idx = tid; idx < TT*NB; idx += 1024) {
        int i = idx >> 5, cc = idx & 31;
        PsS[i*33+cc] = Pg[i*32+cc];
      }
    }
    // ================= update slice x =================
    int jbase = x*128;
    for (int idx = tid; idx < NB*128; idx += 1024) {
      int k = idx >> 7, cc = idx & 127;
      Rs[k*132+cc] = src[(size_t)smap[k0+k]*TT + jbase + cc];
    }
    __syncthreads();
    int tx = tid & 31, ty = tid >> 5;
    int j = jbase + tx*4;
    if (j >= k0 && j < k0 + NB) {
      int pc = j - k0;
      for (int rr = 0; rr < 4; ++rr) {
        int i0 = rr*128 + ty*4;
#pragma unroll
        for (int q = 0; q < 4; ++q) {
          int i = i0 + q;
          *(float4*)(dst + (size_t)i*TT + j) = *(const float4*)(Pg + (size_t)i*32 + pc);
        }
      }
    } else {
      for (int rr = 0; rr < 4; ++rr) {
        int i0 = rr*128 + ty*4;
        float acc[4][4] = {};
#pragma unroll 8
        for (int k = 0; k < NB; ++k) {
          float4 rv = *(const float4*)(Rs + k*132 + tx*4);
          float p0 = PsS[(i0+0)*33+k], p1 = PsS[(i0+1)*33+k];
          float p2 = PsS[(i0+2)*33+k], p3 = PsS[(i0+3)*33+k];
          acc[0][0]+=p0*rv.x; acc[0][1]+=p0*rv.y; acc[0][2]+=p0*rv.z; acc[0][3]+=p0*rv.w;
          acc[1][0]+=p1*rv.x; acc[1][1]+=p1*rv.y; acc[1][2]+=p1*rv.z; acc[1][3]+=p1*rv.w;
          acc[2][0]+=p2*rv.x; acc[2][1]+=p2*rv.y; acc[2][2]+=p2*rv.z; acc[2][3]+=p2*rv.w;
          acc[3][0]+=p3*rv.x; acc[3][1]+=p3*rv.y; acc[3][2]+=p3*rv.z; acc[3][3]+=p3*rv.w;
        }
#pragma unroll
        for (int q = 0; q < 4; ++q) {
          int i = i0 + q;
          float4 res;
          if (i >= k0 && i < k0 + NB) res = make_float4(0.f,0.f,0.f,0.f);
          else res = *(const float4*)(src + (size_t)smap[i]*TT + j);
          res.x += acc[q][0]; res.y += acc[q][1]; res.z += acc[q][2]; res.w += acc[q][3];
          *(float4*)(dst + (size_t)i*TT + j) = res;
        }
      }
    }
    __threadfence();
    __syncthreads();
    if (tid == 0) atomicAdd(&g_done[b], 1);
  }
}

// perm_k: compute column permutation arr, diag dg, and the p_root row (fused).
__global__ void perm_k(float* __restrict__ out2) {
  __shared__ int arr[TT];
  int b = blockIdx.x, tid = threadIdx.x;
  if (tid == 0) {
    for (int j = 0; j < TT; ++j) arr[j] = j;
    for (int l = TT-1; l >= 0; --l) {
      int p = g_piv[b*TT + l];
      if (p != l) { int t = arr[l]; arr[l] = arr[p]; arr[p] = t; }
    }
  }
  __syncthreads();
  const float* a = g_L + (size_t)b*TT*TT;
  int j = tid;
  g_arr[b*TT + j] = arr[j];
  g_dg[b*TT + j] = a[(size_t)j*TT + arr[j]];
  out2[(size_t)b*TT1*TT + j] = g_ar[b*TT + j] * a[(size_t)j*TT + arr[0]];
}

// pij with on-the-fly column permutation (reads g_L directly; no gathered copy)
__global__ __launch_bounds__(1024) void pij_k(float* __restrict__ out2) {
  __shared__ float Ts[32][33];
  __shared__ int sarr[32];
  int b = blockIdx.z;
  int i0 = blockIdx.y*32, j0 = blockIdx.x*32;
  int tx = threadIdx.x, ty = threadIdx.y;
  const float* Lf = g_L + (size_t)b*TT*TT;
  if (ty == 0) sarr[tx] = g_arr[b*TT + i0 + tx];
  __syncthreads();
  Ts[ty][tx] = Lf[(size_t)(j0+ty)*TT + sarr[tx]];   // Linv[j0+ty][i0+tx]
  __syncthreads();
  int i = i0 + ty, j = j0 + tx;
  float av  = g_A[(size_t)b*TT*TT + (size_t)i*TT + j];
  float dj  = (j > 0) ? g_dg[b*TT + j] : 0.0f;
  float lji = (i > 0) ? Ts[tx][ty] : 0.0f;
  out2[(size_t)b*TT1*TT + (size_t)(i+1)*TT + j] = av * (dj - lji);
}

// ---------------- tf32 tensor-core GEMM (double-buffered pipeline) ----------------
#define TFA 136
#define TFB 72
__device__ __forceinline__ float f2tf(float f) {
  unsigned u; asm("cvt.rna.tf32.f32 %0, %1;" : "=r"(u) : "f"(f));
  return __uint_as_float(u);
}
__device__ __forceinline__ void mma_tf32(float* d, const unsigned* a, unsigned b0, unsigned b1) {
  asm volatile("mma.sync.aligned.m16n8k8.row.col.f32.tf32.tf32.f32 "
    "{%0,%1,%2,%3}, {%4,%5,%6,%7}, {%8,%9}, {%0,%1,%2,%3};"
    : "+f"(d[0]), "+f"(d[1]), "+f"(d[2]), "+f"(d[3])
    : "r"(a[0]), "r"(a[1]), "r"(a[2]), "r"(a[3]), "r"(b0), "r"(b1));
}
template<int MODE, bool SPLIT>
__global__ __launch_bounds__(256)
void tgemm_k(const float* __restrict__ A, int lda, long long sA,
             const float* __restrict__ B, int ldb, long long sB,
             float* __restrict__ C, int ldc, long long sC,
             int K, const float* __restrict__ bias, int act, const int* __restrict__ seq,
             const float* __restrict__ aux)
{
  __shared__ __align__(16) float As[2][16*TFA];
  __shared__ __align__(16) float Bs[2][16*TFB];
  int tid = threadIdx.x;
  int m0 = blockIdx.y*128, n0 = blockIdx.x*64;
  const float* Ab = A + (size_t)blockIdx.z*sA;
  const float* Bb = B + (size_t)blockIdx.z*sB;
  float* Cb = C + (size_t)blockIdx.z*sC;
  int warp = tid>>5, lane = tid&31;
  int wm = (warp&3)*32, wn = (warp>>2)*32;
  int g = lane>>2, la3 = lane&3;
  float acc[2][4][4];
#pragma unroll
  for(int a=0;a<2;a++)
#pragma unroll
    for(int b=0;b<4;b++)
#pragma unroll
      for(int c=0;c<4;c++) acc[a][b][c]=0.f;

  const int NT = K >> 4;
  float4 va0, va1, vb;

#define TG_LOAD(k0) do { \
    if (MODE == 2) { \
      int kr0 = tid >> 5, c40 = (tid & 31)*4; \
      va0 = *(const float4*)(Ab + (size_t)((k0)+kr0)*lda + m0 + c40); \
      int i1 = tid + 256; int kr1 = i1 >> 5, c41 = (i1 & 31)*4; \
      va1 = *(const float4*)(Ab + (size_t)((k0)+kr1)*lda + m0 + c41); \
    } else { \
      int r0 = tid >> 2, c40 = (tid & 3)*4; \
      va0 = *(const float4*)(Ab + (size_t)(m0+r0)*lda + (k0) + c40); \
      int i1 = tid + 256; int r1 = i1 >> 2, c41 = (i1 & 3)*4; \
      va1 = *(const float4*)(Ab + (size_t)(m0+r1)*lda + (k0) + c41); \
    } \
    if (MODE == 0) { \
      int r = tid >> 2, c4 = (tid & 3)*4; \
      vb = *(const float4*)(Bb + (size_t)(n0+r)*ldb + (k0) + c4); \
    } else { \
      int kr = tid >> 4, c4 = (tid & 15)*4; \
      vb = *(const float4*)(Bb + (size_t)((k0)+kr)*ldb + n0 + c4); \
    } \
  } while (0)

#define TG_STORE(s) do { \
    float4 w0 = va0, w1 = va1, wb = vb; \
    if (!SPLIT) { \
      w0.x = f2tf(w0.x); w0.y = f2tf(w0.y); w0.z = f2tf(w0.z); w0.w = f2tf(w0.w); \
      w1.x = f2tf(w1.x); w1.y = f2tf(w1.y); w1.z = f2tf(w1.z); w1.w = f2tf(w1.w); \
      wb.x = f2tf(wb.x); wb.y = f2tf(wb.y); wb.z = f2tf(wb.z); wb.w = f2tf(wb.w); \
    } \
    if (MODE == 2) { \
      int kr0 = tid >> 5, c40 = (tid & 31)*4; \
      *(float4*)(As[s] + kr0*TFA + c40) = w0; \
      int i1 = tid + 256; int kr1 = i1 >> 5, c41 = (i1 & 31)*4; \
      *(float4*)(As[s] + kr1*TFA + c41) = w1; \
    } else { \
      int r0 = tid >> 2, c40 = (tid & 3)*4; \
      As[s][(c40+0)*TFA + r0] = w0.x; As[s][(c40+1)*TFA + r0] = w0.y; \
      As[s][(c40+2)*TFA + r0] = w0.z; As[s][(c40+3)*TFA + r0] = w0.w; \
      int i1 = tid + 256; int r1 = i1 >> 2, c41 = (i1 & 3)*4; \
      As[s][(c41+0)*TFA + r1] = w1.x; As[s][(c41+1)*TFA + r1] = w1.y; \
      As[s][(c41+2)*TFA + r1] = w1.z; As[s][(c41+3)*TFA + r1] = w1.w; \
    } \
    if (MODE == 0) { \
      int r = tid >> 2, c4 = (tid & 3)*4; \
      Bs[s][(c4+0)*TFB + r] = wb.x; Bs[s][(c4+1)*TFB + r] = wb.y; \
      Bs[s][(c4+2)*TFB + r] = wb.z; Bs[s][(c4+3)*TFB + r] = wb.w; \
    } else { \
      int kr = tid >> 4, c4 = (tid & 15)*4; \
      *(float4*)(Bs[s] + kr*TFB + c4) = wb; \
    } \
  } while (0)

  TG_LOAD(0);
  TG_STORE(0);
  __syncthreads();

  for (int t = 0; t < NT; ++t) {
    int cb = t & 1;
    if (t+1 < NT) TG_LOAD((t+1)*16);
#pragma unroll
    for (int ks = 0; ks < 2; ++ks) {
      int kb = ks*8;
      unsigned ah[2][4], al[2][4];
#pragma unroll
      for (int mt = 0; mt < 2; ++mt) {
        const float* ap = As[cb] + (kb + la3)*TFA + wm + mt*16 + g;
        float f0 = ap[0], f1 = ap[8], f2 = ap[4*TFA], f3 = ap[4*TFA + 8];
        if (SPLIT) {
          float h0 = f2tf(f0), h1 = f2tf(f1), h2 = f2tf(f2), h3 = f2tf(f3);
          ah[mt][0] = __float_as_uint(h0); al[mt][0] = __float_as_uint(f2tf(f0 - h0));
          ah[mt][1] = __float_as_uint(h1); al[mt][1] = __float_as_uint(f2tf(f1 - h1));
          ah[mt][2] = __float_as_uint(h2); al[mt][2] = __float_as_uint(f2tf(f2 - h2));
          ah[mt][3] = __float_as_uint(h3); al[mt][3] = __float_as_uint(f2tf(f3 - h3));
        } else {
          ah[mt][0] = __float_as_uint(f0); ah[mt][1] = __float_as_uint(f1);
          ah[mt][2] = __float_as_uint(f2); ah[mt][3] = __float_as_uint(f3);
        }
      }
#pragma unroll
      for (int nt = 0; nt < 4; ++nt) {
        const float* bp = Bs[cb] + (kb + la3)*TFB + wn + nt*8 + g;
        float bf0 = bp[0], bf1 = bp[4*TFB];
        unsigned bh0, bh1, bl0, bl1;
        if (SPLIT) {
          float h0 = f2tf(bf0), h1 = f2tf(bf1);
          bh0 = __float_as_uint(h0); bl0 = __float_as_uint(f2tf(bf0 - h0));
          bh1 = __float_as_uint(h1); bl1 = __float_as_uint(f2tf(bf1 - h1));
        } else {
          bh0 = __float_as_uint(bf0); bh1 = __float_as_uint(bf1);
          bl0 = bl1 = 0;
        }
#pragma unroll
        for (int mt = 0; mt < 2; ++mt) {
          mma_tf32(acc[mt][nt], ah[mt], bh0, bh1);
          if (SPLIT) {
            mma_tf32(acc[mt][nt], ah[mt], bl0, bl1);
            mma_tf32(acc[mt][nt], al[mt], bh0, bh1);
          }
        }
      }
    }
    if (t+1 < NT) TG_STORE(cb ^ 1);
    __syncthreads();
  }

  int len = (act == 3) ? seq[blockIdx.z] : 0;
#pragma unroll
  for (int mt = 0; mt < 2; ++mt) {
    int mrow = m0 + wm + mt*16 + g;
#pragma unroll
    for (int nt = 0; nt < 4; ++nt) {
      int ncol = n0 + wn + nt*8 + la3*2;
      float b0v = 0.f, b1v = 0.f;
      if (bias && act != 4) { b0v = bias[ncol]; b1v = bias[ncol+1]; }
      float v[4] = { acc[mt][nt][0] + b0v, acc[mt][nt][1] + b1v,
                     acc[mt][nt][2] + b0v, acc[mt][nt][3] + b1v };
      if (act == 1) {
        v[0]=tanhf(v[0]); v[1]=tanhf(v[1]); v[2]=tanhf(v[2]); v[3]=tanhf(v[3]);
      } else if (act == 2) {
#pragma unroll
        for (int q = 0; q < 4; ++q) v[q] = v[q]>=0.f ? v[q] : 0.01f*v[q];
      } else if (act == 3) {
#pragma unroll
        for (int q = 0; q < 4; ++q) {
          int gi = mrow + (q >= 2 ? 8 : 0);
          int gj = ncol + (q & 1);
          v[q] = (gi != gj && gi < len && gj < len) ? expf(v[q]) : 0.0f;
        }
      } else if (act == 4) {
        float pr0 = aux[(size_t)blockIdx.z*TT1*TT + mrow];
        float pr8 = aux[(size_t)blockIdx.z*TT1*TT + mrow + 8];
        v[0] += pr0*bias[ncol]; v[1] += pr0*bias[ncol+1];
        v[2] += pr8*bias[ncol]; v[3] += pr8*bias[ncol+1];
      }
      *(float2*)(Cb + (size_t)mrow*ldc + ncol) = make_float2(v[0], v[1]);
      *(float2*)(Cb + (size_t)(mrow+8)*ldc + ncol) = make_float2(v[2], v[3]);
    }
  }
#undef TG_LOAD
#undef TG_STORE
}

// ---------------- launch ----------------
extern "C" void kernel_launch(void* const* d_in, const int* in_sizes, int n_in,
                              void* d_out, int out_size) {
  (void)in_sizes; (void)n_in; (void)out_size;
  const float* x     = (const float*)d_in[0];
  const int*   seq   = (const int*)  d_in[1];
  const float* W_tp  = (const float*)d_in[2];
  const float* b_tp  = (const float*)d_in[3];
  const float* W_tc  = (const float*)d_in[4];
  const float* b_tc  = (const float*)d_in[5];
  const float* W_fij = (const float*)d_in[6];
  const float* w_root= (const float*)d_in[7];
  const float* r_emb = (const float*)d_in[8];
  const float* W_r   = (const float*)d_in[9];
  const float* b_r   = (const float*)d_in[10];
  const float* W_pc  = (const float*)d_in[11];
  const float* b_pc  = (const float*)d_in[12];
  float* out1 = (float*)d_out;
  float* out2 = out1 + (size_t)BT*SD;

  float *st,*se,*tp,*tc,*gg,*A,*L,*Li,*cat,*cat2;
  cudaGetSymbolAddress((void**)&st,   g_st);
  cudaGetSymbolAddress((void**)&se,   g_se);
  cudaGetSymbolAddress((void**)&tp,   g_tp);
  cudaGetSymbolAddress((void**)&tc,   g_tc);
  cudaGetSymbolAddress((void**)&gg,   g_gg);
  cudaGetSymbolAddress((void**)&A,    g_A);
  cudaGetSymbolAddress((void**)&L,    g_L);
  cudaGetSymbolAddress((void**)&Li,   g_Li);
  cudaGetSymbolAddress((void**)&cat,  g_cat);
  cudaGetSymbolAddress((void**)&cat2, g_cat2);

  const int INV_SMEM = TT*33*4 + NB*132*4;   // 84480
  cudaFuncSetAttribute(inv_k, cudaFuncAttributeMaxDynamicSharedMemorySize, INV_SMEM);

  const long long sTT = (long long)TT*TT, sTS = (long long)TT*SD,
                  sTH = (long long)TT*HD, sP = (long long)TT1*TT;
  const float* pij = out2 + TT;

  split_k<<<BT*HD/256, 256>>>(x);
  tgemm_k<0,true><<<dim3(4,128,1),256>>>(st, SD, 0, W_tp, SD, 0, tp, SD, 0, SD, b_tp, 1, 0, 0);
  tgemm_k<0,true><<<dim3(4,128,1),256>>>(st, SD, 0, W_tc, SD, 0, tc, SD, 0, SD, b_tc, 1, 0, 0);
  tgemm_k<1,true><<<dim3(4,128,1),256>>>(tp, SD, 0, W_fij, SD, 0, gg, SD, 0, SD, 0, 0, 0, 0);
  tgemm_k<0,true><<<dim3(8,4,BB),256>>>(gg, SD, sTS, tc, SD, sTS, A, TT, sTT, SD, 0, 3, seq, 0);
  root_k<<<BT*32/256, 256>>>(w_root, seq);
  colsum_k<<<dim3(8,BB), 512>>>();
  buildL_k<<<MT/256, 256>>>(seq);
  inv_k<<<dim3(4, BB), 1024, INV_SMEM>>>(L, Li);
  perm_k<<<BB, TT>>>(out2);
  pij_k<<<dim3(16,16,BB), dim3(32,32)>>>(out2);
  tgemm_k<2,false><<<dim3(4,4,BB),256>>>(pij, TT, sP, se, SD, sTS, cat, HD, sTH, TT, r_emb, 4, 0, out2);
  tgemm_k<1,false><<<dim3(4,4,BB),256>>>(pij, TT, sP, se, SD, sTS, cat + SD, HD, sTH, TT, 0, 0, 0, 0);
  tgemm_k<0,false><<<dim3(4,128,1),256>>>(cat, HD, 0, W_r, HD, 0, cat2, HD, 0, HD, b_r, 2, 0, 0);
  tgemm_k<1,false><<<dim3(4,4,BB),256>>>(pij, TT, sP, cat2, HD, sTH, cat2 + SD, HD, sTH, TT, 0, 0, 0, 0);
  tgemm_k<0,false><<<dim3(4,128,1),256>>>(cat2, HD, 0, W_pc, HD, 0, out1, SD, 0, HD, b_pc, 2, 0, 0);
}